// round 1
// baseline (speedup 1.0000x reference)
#include <cuda_runtime.h>
#include <math.h>

#define NB    32
#define SQ    32
#define HH    1024
#define NHEAD 16
#define HS    64
#define NLAY  4
#define THIST 8
#define TACT  8
#define HIN   512
#define AIN   64

#define TOK_ELEMS (NB*SQ*HH)   // 1048576

// ---------------- scratch (device globals; no allocation) ----------------
__device__ float g_pe[SQ*HH];
__device__ float g_tokens[TOK_ELEMS];
__device__ float g_h[TOK_ELEMS];
__device__ float g_prev[NLAY*TOK_ELEMS];
__device__ float g_q[TOK_ELEMS];
__device__ float g_kb[TOK_ELEMS];
__device__ float g_vb[TOK_ELEMS];
__device__ float g_ctx[TOK_ELEMS];
__device__ float g_tmp[TOK_ELEMS];
__device__ float g_spart[16*NB*HIN];
__device__ float g_srelu[NB*HIN];

// ---------------- positional encoding ----------------
__global__ void pe_kernel(float* __restrict__ pe)
{
    int s = blockIdx.x;
    for (int h = threadIdx.x; h < HH; h += 256) {
        double angle = (double)s / pow(10000.0, (double)(2*(h/2)) / (double)HH);
        pe[s*HH + h] = (h & 1) ? (float)cos(angle) : (float)sin(angle);
    }
}

__global__ void zero4_kernel(float* __restrict__ p)
{
    int idx = blockIdx.x*256 + threadIdx.x;
    ((float4*)p)[idx] = make_float4(0.f,0.f,0.f,0.f);
}

// ---------------- small row GEMM + relu into tokens ----------------
// mode 1: drow = (r>>3)*32 + (r&7)*2      (history states)
// mode 2: drow = (r>>3)*32 + (r&7)*2 + 1  (history actions)
// mode 3: drow = r*32 + off               (s / action / next-state tokens)
__global__ void vecmat_relu(const float* __restrict__ X, int xstride,
                            const float* __restrict__ W, int K,
                            int mode, int off, float* __restrict__ tokens)
{
    int r = blockIdx.x;
    __shared__ float xs[512];
    for (int k = threadIdx.x; k < K; k += 256) xs[k] = X[r*xstride + k];
    __syncthreads();
    int drow;
    if      (mode == 1) drow = (r>>3)*32 + ((r&7)<<1);
    else if (mode == 2) drow = (r>>3)*32 + ((r&7)<<1) + 1;
    else                drow = r*32 + off;
    int c = blockIdx.y*256 + threadIdx.x;
    float acc = 0.f;
    for (int k = 0; k < K; k++) acc = fmaf(xs[k], W[k*HH + c], acc);
    tokens[drow*HH + c] = fmaxf(acc, 0.f);
}

// ---------------- h = tokens + pe (valid rows) ----------------
__global__ void addpe_kernel(const float* __restrict__ tokens,
                             const float* __restrict__ pe,
                             float* __restrict__ h, int L)
{
    int idx = blockIdx.x*256 + threadIdx.x;   // float4 index
    float4 t = ((const float4*)tokens)[idx];
    int e = idx << 2;
    int srow = (e >> 10) & 31;
    if (srow < L) {
        float4 p = ((const float4*)pe)[(srow*HH + (e & 1023)) >> 2];
        t.x += p.x; t.y += p.y; t.z += p.z; t.w += p.w;
    }
    ((float4*)h)[idx] = t;
}

// ---------------- 64x64-tile SGEMM, M=N=K=1024 row-major ----------------
__device__ __forceinline__ void sgemm_body(const float* __restrict__ A,
                                           const float* __restrict__ B,
                                           float* __restrict__ C)
{
    __shared__ float As[16][64];   // transposed: As[k][m]
    __shared__ float Bs[16][64];
    const int tid = threadIdx.x;
    const int tx = tid & 15, ty = tid >> 4;
    const int bm = blockIdx.y << 6, bn = blockIdx.x << 6;
    const int arow = tid >> 2, ac4 = (tid & 3) << 2;
    const int brow = tid >> 4, bc4 = (tid & 15) << 2;
    float acc[4][4] = {};
    const float* Aptr = A + (bm + arow)*HH + ac4;
    const float* Bptr = B + brow*HH + bn + bc4;
    float4 a = *(const float4*)Aptr;
    float4 b = *(const float4*)Bptr;
    for (int k0 = 0; k0 < 1024; k0 += 16) {
        As[ac4+0][arow] = a.x; As[ac4+1][arow] = a.y;
        As[ac4+2][arow] = a.z; As[ac4+3][arow] = a.w;
        *(float4*)&Bs[brow][bc4] = b;
        __syncthreads();
        if (k0 + 16 < 1024) {
            a = *(const float4*)(Aptr + k0 + 16);
            b = *(const float4*)(Bptr + (k0 + 16)*HH);
        }
        #pragma unroll
        for (int kk = 0; kk < 16; kk++) {
            float4 av = *(const float4*)&As[kk][ty<<2];
            float4 bv = *(const float4*)&Bs[kk][tx<<2];
            acc[0][0] = fmaf(av.x, bv.x, acc[0][0]);
            acc[0][1] = fmaf(av.x, bv.y, acc[0][1]);
            acc[0][2] = fmaf(av.x, bv.z, acc[0][2]);
            acc[0][3] = fmaf(av.x, bv.w, acc[0][3]);
            acc[1][0] = fmaf(av.y, bv.x, acc[1][0]);
            acc[1][1] = fmaf(av.y, bv.y, acc[1][1]);
            acc[1][2] = fmaf(av.y, bv.z, acc[1][2]);
            acc[1][3] = fmaf(av.y, bv.w, acc[1][3]);
            acc[2][0] = fmaf(av.z, bv.x, acc[2][0]);
            acc[2][1] = fmaf(av.z, bv.y, acc[2][1]);
            acc[2][2] = fmaf(av.z, bv.z, acc[2][2]);
            acc[2][3] = fmaf(av.z, bv.w, acc[2][3]);
            acc[3][0] = fmaf(av.w, bv.x, acc[3][0]);
            acc[3][1] = fmaf(av.w, bv.y, acc[3][1]);
            acc[3][2] = fmaf(av.w, bv.z, acc[3][2]);
            acc[3][3] = fmaf(av.w, bv.w, acc[3][3]);
        }
        __syncthreads();
    }
    #pragma unroll
    for (int r = 0; r < 4; r++) {
        float4 o = make_float4(acc[r][0], acc[r][1], acc[r][2], acc[r][3]);
        *(float4*)(C + (bm + (ty<<2) + r)*HH + bn + (tx<<2)) = o;
    }
}

__global__ void sgemm_k(const float* __restrict__ A, const float* __restrict__ B,
                        float* __restrict__ C)
{
    sgemm_body(A, B, C);
}

__global__ void sgemm_qkv_k(const float* __restrict__ qk, const float* __restrict__ h,
                            const float* __restrict__ Wq, const float* __restrict__ Wk,
                            const float* __restrict__ Wv,
                            float* __restrict__ Q, float* __restrict__ K,
                            float* __restrict__ V)
{
    int z = blockIdx.z;
    const float* A = (z == 2) ? h : qk;
    const float* B = (z == 0) ? Wq : (z == 1) ? Wk : Wv;
    float*       C = (z == 0) ? Q  : (z == 1) ? K  : V;
    sgemm_body(A, B, C);
}

// ---------------- attention (one block per (b, head)) ----------------
__global__ void attn_kernel(int L, const float* __restrict__ Q,
                            const float* __restrict__ K,
                            const float* __restrict__ V,
                            float* __restrict__ ctx)
{
    __shared__ float Qs[32][64];
    __shared__ float KsT[64][33];
    __shared__ float Vs[32][64];
    __shared__ float P[32][33];
    int tid = threadIdx.x;
    int b = blockIdx.x >> 4, hd = blockIdx.x & 15;
    const float* qb = Q + b*SQ*HH + hd*HS;
    const float* kb = K + b*SQ*HH + hd*HS;
    const float* vb = V + b*SQ*HH + hd*HS;
    #pragma unroll
    for (int t = 0; t < 2; t++) {
        int f = tid + t*256;
        int row = f >> 4, c4 = (f & 15) << 2;
        float4 q4 = *(const float4*)(qb + row*HH + c4);
        *(float4*)&Qs[row][c4] = q4;
        float4 k4 = *(const float4*)(kb + row*HH + c4);
        KsT[c4+0][row] = k4.x; KsT[c4+1][row] = k4.y;
        KsT[c4+2][row] = k4.z; KsT[c4+3][row] = k4.w;
        float4 v4 = *(const float4*)(vb + row*HH + c4);
        *(float4*)&Vs[row][c4] = v4;
    }
    __syncthreads();
    // scores
    #pragma unroll
    for (int t = 0; t < 4; t++) {
        int p = tid + t*256;
        int qr = p >> 5, kr = p & 31;
        float sc = 0.f;
        #pragma unroll
        for (int d = 0; d < 64; d++) sc = fmaf(Qs[qr][d], KsT[d][kr], sc);
        P[qr][kr] = sc * 0.125f;
    }
    __syncthreads();
    // softmax per row (warp w handles rows w, w+8, w+16, w+24)
    int w = tid >> 5, lane = tid & 31;
    #pragma unroll
    for (int r = 0; r < 4; r++) {
        int qr = w + r*8;
        bool vq = qr < L, vk = lane < L;
        float v = (vq && vk) ? P[qr][lane] : -1e30f;
        float mx = v;
        #pragma unroll
        for (int off = 16; off > 0; off >>= 1)
            mx = fmaxf(mx, __shfl_xor_sync(0xFFFFFFFFu, mx, off));
        float e = (vq && vk) ? expf(v - mx) : 0.f;
        float sm = e;
        #pragma unroll
        for (int off = 16; off > 0; off >>= 1)
            sm += __shfl_xor_sync(0xFFFFFFFFu, sm, off);
        P[qr][lane] = vq ? (e / sm) : 0.f;
    }
    __syncthreads();
    // out = P @ V
    float* cb = ctx + b*SQ*HH + hd*HS;
    #pragma unroll
    for (int t = 0; t < 8; t++) {
        int e = tid + t*256;
        int qr = e >> 6, d = e & 63;
        float acc = 0.f;
        #pragma unroll
        for (int k = 0; k < 32; k++) acc = fmaf(P[qr][k], Vs[k][d], acc);
        cb[qr*HH + d] = acc;
    }
}

// ---------------- LayerNorm(x + y) ----------------
__global__ void ln_kernel(const float* __restrict__ X, const float* __restrict__ Y,
                          const float* __restrict__ gam, const float* __restrict__ bet,
                          float* __restrict__ out, float* __restrict__ out2)
{
    int row = blockIdx.x;
    int tid = threadIdx.x;
    const float* x = X + row*HH;
    const float* y = Y + row*HH;
    float v[4];
    float s = 0.f;
    #pragma unroll
    for (int i = 0; i < 4; i++) { v[i] = x[tid + i*256] + y[tid + i*256]; s += v[i]; }
    __shared__ float red[256];
    red[tid] = s; __syncthreads();
    for (int st = 128; st > 0; st >>= 1) {
        if (tid < st) red[tid] += red[tid + st];
        __syncthreads();
    }
    float mean = red[0] * (1.f/1024.f);
    __syncthreads();
    float q = 0.f;
    #pragma unroll
    for (int i = 0; i < 4; i++) { float d = v[i] - mean; q = fmaf(d, d, q); }
    red[tid] = q; __syncthreads();
    for (int st = 128; st > 0; st >>= 1) {
        if (tid < st) red[tid] += red[tid + st];
        __syncthreads();
    }
    float inv = rsqrtf(red[0] * (1.f/1024.f) + 1e-5f);
    #pragma unroll
    for (int i = 0; i < 4; i++) {
        int c = tid + i*256;
        float o = (v[i] - mean) * inv * gam[c] + bet[c];
        out[row*HH + c] = o;
        if (out2) out2[row*HH + c] = o;
    }
}

// ---------------- r = sigmoid(hf @ Wr) ----------------
__global__ void r_kernel(const float* __restrict__ hf, const float* __restrict__ Wr,
                         float* __restrict__ out_r, int i)
{
    int b = blockIdx.x;
    const float* x = hf + b*SQ*HH;
    float acc = 0.f;
    for (int k = threadIdx.x; k < SQ*HH; k += 256) acc = fmaf(x[k], Wr[k], acc);
    __shared__ float red[256];
    red[threadIdx.x] = acc; __syncthreads();
    for (int st = 128; st > 0; st >>= 1) {
        if (threadIdx.x < st) red[threadIdx.x] += red[threadIdx.x + st];
        __syncthreads();
    }
    if (threadIdx.x == 0) out_r[b*TACT + i] = 1.f / (1.f + expf(-red[0]));
}

// ---------------- s_new partials: [32,32768]@[32768,512], split-K 16 ----------------
__global__ void snew_kernel(const float* __restrict__ hf, const float* __restrict__ Wso,
                            float* __restrict__ spart)
{
    __shared__ float As[32][36];
    __shared__ float Bs[32][64];
    int tid = threadIdx.x;
    int n0 = blockIdx.x << 6;
    int k0 = blockIdx.y << 11;
    int col = tid & 63;
    int rg  = tid >> 6;  // 0..3
    int ar = tid >> 3, ac4 = (tid & 7) << 2;
    float acc[8] = {};
    for (int kc = 0; kc < 2048; kc += 32) {
        float4 av = *(const float4*)(hf + ar*(SQ*HH) + k0 + kc + ac4);
        As[ar][ac4+0] = av.x; As[ar][ac4+1] = av.y;
        As[ar][ac4+2] = av.z; As[ar][ac4+3] = av.w;
        #pragma unroll
        for (int t = 0; t < 2; t++) {
            int f = tid + t*256;
            int kk = f >> 4, c4 = (f & 15) << 2;
            *(float4*)&Bs[kk][c4] = *(const float4*)(Wso + (k0 + kc + kk)*HIN + n0 + c4);
        }
        __syncthreads();
        #pragma unroll 8
        for (int kk = 0; kk < 32; kk++) {
            float bv = Bs[kk][col];
            #pragma unroll
            for (int r8 = 0; r8 < 8; r8++)
                acc[r8] = fmaf(As[rg*8 + r8][kk], bv, acc[r8]);
        }
        __syncthreads();
    }
    #pragma unroll
    for (int r8 = 0; r8 < 8; r8++)
        spart[blockIdx.y*(NB*HIN) + (rg*8 + r8)*HIN + n0 + col] = acc[r8];
}

__global__ void fin_kernel(const float* __restrict__ spart, float* __restrict__ srelu,
                           float* __restrict__ out_s, int i)
{
    int idx = blockIdx.x*256 + threadIdx.x;   // 16384
    float v = 0.f;
    #pragma unroll
    for (int p = 0; p < 16; p++) v += spart[p*(NB*HIN) + idx];
    v = fmaxf(v, 0.f);
    srelu[idx] = v;
    int b = idx >> 9, n = idx & 511;
    out_s[(b*TACT + i)*HIN + n] = v;
}

// ---------------- host orchestration ----------------
extern "C" void kernel_launch(void* const* d_in, const int* in_sizes, int n_in,
                              void* d_out, int out_size)
{
    const float* history_s = (const float*)d_in[0];
    const float* history_a = (const float*)d_in[1];
    const float* s_in      = (const float*)d_in[2];
    const float* a_list    = (const float*)d_in[3];
    const float* Ws        = (const float*)d_in[4];
    const float* Wa        = (const float*)d_in[5];
    const float* Wq        = (const float*)d_in[6];
    const float* Wk        = (const float*)d_in[7];
    const float* Wv        = (const float*)d_in[8];
    const float* Wo        = (const float*)d_in[9];
    const float* Wfc       = (const float*)d_in[10];
    const float* ln1_g     = (const float*)d_in[11];
    const float* ln1_b     = (const float*)d_in[12];
    const float* ln2_g     = (const float*)d_in[13];
    const float* ln2_b     = (const float*)d_in[14];
    const float* Wr        = (const float*)d_in[15];
    const float* Wso       = (const float*)d_in[16];

    float* out_r = (float*)d_out;             // [B, TA]
    float* out_s = out_r + NB*TACT;           // [B, TA, HIN]

    void* p;
    cudaGetSymbolAddress(&p, g_pe);     float* pe     = (float*)p;
    cudaGetSymbolAddress(&p, g_tokens); float* tokens = (float*)p;
    cudaGetSymbolAddress(&p, g_h);      float* h      = (float*)p;
    cudaGetSymbolAddress(&p, g_prev);   float* prev   = (float*)p;
    cudaGetSymbolAddress(&p, g_q);      float* qb     = (float*)p;
    cudaGetSymbolAddress(&p, g_kb);     float* kb     = (float*)p;
    cudaGetSymbolAddress(&p, g_vb);     float* vb     = (float*)p;
    cudaGetSymbolAddress(&p, g_ctx);    float* ctx    = (float*)p;
    cudaGetSymbolAddress(&p, g_tmp);    float* tmp    = (float*)p;
    cudaGetSymbolAddress(&p, g_spart);  float* spart  = (float*)p;
    cudaGetSymbolAddress(&p, g_srelu);  float* srelu  = (float*)p;

    pe_kernel<<<SQ, 256>>>(pe);
    zero4_kernel<<<TOK_ELEMS/1024, 256>>>(tokens);

    // history embeddings + initial state token
    vecmat_relu<<<dim3(NB*THIST, 4), 256>>>(history_s, HIN, Ws, HIN, 1, 0, tokens);
    vecmat_relu<<<dim3(NB*THIST, 4), 256>>>(history_a, AIN, Wa, AIN, 2, 0, tokens);
    vecmat_relu<<<dim3(NB, 4), 256>>>(s_in, HIN, Ws, HIN, 3, 16, tokens);

    for (int i = 0; i < TACT; i++) {
        int posA = 2*THIST + 1 + 2*i;
        int L = posA + 1;
        // action token
        vecmat_relu<<<dim3(NB, 4), 256>>>(a_list + i*AIN, TACT*AIN, Wa, AIN, 3, posA, tokens);
        // h = tokens + pe (valid rows)
        addpe_kernel<<<TOK_ELEMS/1024, 256>>>(tokens, pe, h, L);
        for (int j = 0; j < NLAY; j++) {
            const float* qk = (i == 0) ? h : (prev + j*TOK_ELEMS);
            sgemm_qkv_k<<<dim3(16, 16, 3), 256>>>(qk, h,
                Wq + j*HH*HH, Wk + j*HH*HH, Wv + j*HH*HH, qb, kb, vb);
            attn_kernel<<<NB*NHEAD, 256>>>(L, qb, kb, vb, ctx);
            sgemm_k<<<dim3(16, 16), 256>>>(ctx, Wo + j*HH*HH, tmp);
            ln_kernel<<<NB*SQ, 256>>>(h, tmp, ln1_g + j*HH, ln1_b + j*HH, h, (float*)0);
            sgemm_k<<<dim3(16, 16), 256>>>(h, Wfc + j*HH*HH, tmp);
            ln_kernel<<<NB*SQ, 256>>>(h, tmp, ln2_g + j*HH, ln2_b + j*HH, h, prev + j*TOK_ELEMS);
        }
        r_kernel<<<NB, 256>>>(h, Wr, out_r, i);
        snew_kernel<<<dim3(8, 16), 256>>>(h, Wso, spart);
        fin_kernel<<<64, 256>>>(spart, srelu, out_s, i);
        if (i + 1 < TACT)
            vecmat_relu<<<dim3(NB, 4), 256>>>(srelu, HIN, Ws, HIN, 3, posA + 1, tokens);
    }
}

// round 4
// speedup vs baseline: 2.3980x; 2.3980x over previous
#include <cuda_runtime.h>
#include <cuda_bf16.h>
#include <cstdint>
#include <math.h>

#define NB    32
#define SQ    32
#define HH    1024
#define NHEAD 16
#define HS    64
#define NLAY  4
#define THIST 8
#define TACT  8
#define HIN   512
#define AIN   64

#define TOK_ELEMS (NB*SQ*HH)   // 1048576
#define WMAT      (HH*HH)      // 1048576

// ---------------- scratch (device globals; no allocation) ----------------
__device__ float g_pe[SQ*HH];
__device__ float g_tokens[TOK_ELEMS];
__device__ float g_h[TOK_ELEMS];
__device__ float g_q[TOK_ELEMS];
__device__ float g_kbuf[TOK_ELEMS];
__device__ float g_vbuf[TOK_ELEMS];
__device__ float g_tmp[TOK_ELEMS];
__device__ float g_spart[16*NB*HIN];
__device__ float g_srelu[NB*HIN];
// bf16 hi/lo activation buffers
__device__ __nv_bfloat16 g_hh[TOK_ELEMS];
__device__ __nv_bfloat16 g_hl[TOK_ELEMS];
__device__ __nv_bfloat16 g_ctxh[TOK_ELEMS];
__device__ __nv_bfloat16 g_ctxl[TOK_ELEMS];
__device__ __nv_bfloat16 g_phh[NLAY*TOK_ELEMS];
__device__ __nv_bfloat16 g_phl[NLAY*TOK_ELEMS];
// transposed bf16 hi/lo weights: 20 matrices [N=1024, K=1024]
__device__ __nv_bfloat16 g_WhT[20*WMAT];
__device__ __nv_bfloat16 g_WlT[20*WMAT];

// ---------------- helpers ----------------
__device__ __forceinline__ uint32_t s2u(const void* p) {
    uint32_t a;
    asm("{ .reg .u64 t; cvta.to.shared.u64 t, %1; cvt.u32.u64 %0, t; }" : "=r"(a) : "l"(p));
    return a;
}

__device__ __forceinline__ void split2(float v, __nv_bfloat16& hi, __nv_bfloat16& lo) {
    hi = __float2bfloat16(v);
    lo = __float2bfloat16(v - __bfloat162float(hi));
}

#define LDM4(r, addr) \
    asm volatile("ldmatrix.sync.aligned.m8n8.x4.shared.b16 {%0,%1,%2,%3}, [%4];" \
        : "=r"((r)[0]), "=r"((r)[1]), "=r"((r)[2]), "=r"((r)[3]) : "r"(addr))

#define MMA_BF16(d, a, b0v, b1v) \
    asm volatile("mma.sync.aligned.m16n8k16.row.col.f32.bf16.bf16.f32 " \
        "{%0,%1,%2,%3}, {%4,%5,%6,%7}, {%8,%9}, {%0,%1,%2,%3};" \
        : "+f"((d)[0]), "+f"((d)[1]), "+f"((d)[2]), "+f"((d)[3]) \
        : "r"((a)[0]), "r"((a)[1]), "r"((a)[2]), "r"((a)[3]), "r"(b0v), "r"(b1v))

#define CP_ASYNC16(sa, gp) \
    asm volatile("cp.async.cg.shared.global [%0], [%1], 16;" :: "r"(sa), "l"(gp))
#define CP_COMMIT()  asm volatile("cp.async.commit_group;" ::: "memory")
#define CP_WAIT1()   asm volatile("cp.async.wait_group 1;" ::: "memory")

// ---------------- weight transpose + bf16 split: W[K,N] -> WT[N,K] hi/lo ----------------
__global__ void wconv_kernel(const float* __restrict__ Wq, const float* __restrict__ Wk,
                             const float* __restrict__ Wv, const float* __restrict__ Wo,
                             const float* __restrict__ Wfc,
                             __nv_bfloat16* __restrict__ WhT, __nv_bfloat16* __restrict__ WlT)
{
    int z = blockIdx.z;                 // 0..19 = type*4 + layer
    int type = z >> 2, layer = z & 3;
    const float* bases[5] = {Wq, Wk, Wv, Wo, Wfc};
    const float* W = bases[type] + (size_t)layer * WMAT;
    __shared__ float t[32][33];
    int x0 = blockIdx.x * 32;  // K
    int y0 = blockIdx.y * 32;  // N
    int tr = threadIdx.x >> 5, tc = threadIdx.x & 31;
    #pragma unroll
    for (int u = 0; u < 4; u++) {
        int r = tr + u * 8;
        t[r][tc] = W[(size_t)(x0 + r) * HH + y0 + tc];
    }
    __syncthreads();
    size_t ob = (size_t)z * WMAT;
    #pragma unroll
    for (int u = 0; u < 4; u++) {
        int r = tr + u * 8;           // local n
        float v = t[tc][r];
        __nv_bfloat16 hi, lo; split2(v, hi, lo);
        size_t off = ob + (size_t)(y0 + r) * HH + x0 + tc;
        WhT[off] = hi;
        WlT[off] = lo;
    }
}

// ---------------- bf16-split tensor-core GEMM (mma.sync) ----------------
// C[1024,1024] = A[1024,1024] x B^T  (B stored [N,K] bf16, hi/lo)
// CTA tile: 64(M) x 128(N), K-chunk 64, double-buffered cp.async, SW128 swizzle.
// Stage layout (49152 B): Ah[0,8K) Al[8K,16K) Bh[16K,32K) Bl[32K,48K)
#define STAGE 49152
#define GEMM_SMEM (2*STAGE)

__device__ __forceinline__ void issue_stage(uint32_t sbase, int buf,
    const __nv_bfloat16* __restrict__ Ah, const __nv_bfloat16* __restrict__ Al,
    const __nv_bfloat16* __restrict__ Bh, const __nv_bfloat16* __restrict__ Bl,
    int bm, int bn, int k0, int tid)
{
    uint32_t st = sbase + buf * STAGE;
    #pragma unroll
    for (int u = 0; u < 12; u++) {
        int id = tid + u * 256;
        if (id < 1024) {
            int sec = id >> 9;               // 0=Ah 1=Al
            int r = (id & 511) >> 3, c = id & 7;
            const __nv_bfloat16* gp = (sec ? Al : Ah) + (size_t)(bm + r) * HH + k0 + c * 8;
            uint32_t sa = st + sec * 8192 + r * 128 + ((c ^ (r & 7)) << 4);
            CP_ASYNC16(sa, gp);
        } else {
            int sec = (id - 1024) >> 10;     // 0=Bh 1=Bl
            int r = ((id - 1024) & 1023) >> 3, c = id & 7;
            const __nv_bfloat16* gp = (sec ? Bl : Bh) + (size_t)(bn + r) * HH + k0 + c * 8;
            uint32_t sa = st + 16384 + sec * 16384 + r * 128 + ((c ^ (r & 7)) << 4);
            CP_ASYNC16(sa, gp);
        }
    }
    CP_COMMIT();
}

__device__ __forceinline__ void gemm_body(
    const __nv_bfloat16* __restrict__ Ah, const __nv_bfloat16* __restrict__ Al,
    const __nv_bfloat16* __restrict__ Bh, const __nv_bfloat16* __restrict__ Bl,
    float* __restrict__ C)
{
    extern __shared__ char smem[];
    uint32_t sbase = s2u(smem);
    int tid = threadIdx.x, wid = tid >> 5, lane = tid & 31;
    int bm = blockIdx.y << 6, bn = blockIdx.x << 7;
    int warpM = (wid >> 2) << 5;   // 0 / 32
    int warpN = (wid & 3) << 5;    // 0..96

    issue_stage(sbase, 0, Ah, Al, Bh, Bl, bm, bn, 0, tid);
    issue_stage(sbase, 1, Ah, Al, Bh, Bl, bm, bn, 64, tid);

    float acc[2][4][4] = {};

    for (int s = 0; s < 16; s++) {
        CP_WAIT1();
        __syncthreads();
        uint32_t st = sbase + (s & 1) * STAGE;
        #pragma unroll
        for (int kk = 0; kk < 4; kk++) {
            uint32_t ah[2][4], alr[2][4];
            #pragma unroll
            for (int mt = 0; mt < 2; mt++) {
                int r = warpM + mt * 16 + (lane & 15);
                int ch = kk * 2 + (lane >> 4);
                uint32_t ad = st + r * 128 + ((ch ^ (r & 7)) << 4);
                LDM4(ah[mt], ad);
                LDM4(alr[mt], ad + 8192);
            }
            uint32_t bh[2][4], blr[2][4];
            #pragma unroll
            for (int nt = 0; nt < 2; nt++) {
                int r = warpN + nt * 16 + (lane & 7) + ((lane >> 4) << 3);
                int ch = kk * 2 + ((lane >> 3) & 1);
                uint32_t bd = st + 16384 + r * 128 + ((ch ^ (r & 7)) << 4);
                LDM4(bh[nt], bd);
                LDM4(blr[nt], bd + 16384);
            }
            #pragma unroll
            for (int mt = 0; mt < 2; mt++) {
                #pragma unroll
                for (int j = 0; j < 4; j++) {
                    uint32_t b0 = bh[j >> 1][(j & 1) * 2], b1 = bh[j >> 1][(j & 1) * 2 + 1];
                    uint32_t c0 = blr[j >> 1][(j & 1) * 2], c1 = blr[j >> 1][(j & 1) * 2 + 1];
                    MMA_BF16(acc[mt][j], ah[mt], b0, b1);
                    MMA_BF16(acc[mt][j], ah[mt], c0, c1);
                    MMA_BF16(acc[mt][j], alr[mt], b0, b1);
                }
            }
        }
        __syncthreads();
        if (s + 2 < 16)
            issue_stage(sbase, s & 1, Ah, Al, Bh, Bl, bm, bn, (s + 2) << 6, tid);
    }

    #pragma unroll
    for (int mt = 0; mt < 2; mt++) {
        int row = bm + warpM + mt * 16 + (lane >> 2);
        #pragma unroll
        for (int j = 0; j < 4; j++) {
            int col = bn + warpN + j * 8 + ((lane & 3) << 1);
            *(float2*)&C[(size_t)row * HH + col] =
                make_float2(acc[mt][j][0], acc[mt][j][1]);
            *(float2*)&C[(size_t)(row + 8) * HH + col] =
                make_float2(acc[mt][j][2], acc[mt][j][3]);
        }
    }
}

__global__ void __launch_bounds__(256, 1) gemm_tc(
    const __nv_bfloat16* __restrict__ Ah, const __nv_bfloat16* __restrict__ Al,
    const __nv_bfloat16* __restrict__ Bh, const __nv_bfloat16* __restrict__ Bl,
    float* __restrict__ C)
{
    gemm_body(Ah, Al, Bh, Bl, C);
}

// fused Q/K/V: z selects operand set
__global__ void __launch_bounds__(256, 1) gemm_qkv(
    const __nv_bfloat16* __restrict__ qh, const __nv_bfloat16* __restrict__ ql,
    const __nv_bfloat16* __restrict__ hh, const __nv_bfloat16* __restrict__ hl,
    const __nv_bfloat16* __restrict__ WhT, const __nv_bfloat16* __restrict__ WlT,
    size_t sq, size_t sk, size_t sv,
    float* __restrict__ Q, float* __restrict__ K, float* __restrict__ V)
{
    int z = blockIdx.z;
    const __nv_bfloat16* Ah = (z == 2) ? hh : qh;
    const __nv_bfloat16* Al = (z == 2) ? hl : ql;
    size_t off = (z == 0) ? sq : (z == 1) ? sk : sv;
    float* C = (z == 0) ? Q : (z == 1) ? K : V;
    gemm_body(Ah, Al, WhT + off, WlT + off, C);
}

// ---------------- positional encoding ----------------
__global__ void pe_kernel(float* __restrict__ pe)
{
    int s = blockIdx.x;
    for (int h = threadIdx.x; h < HH; h += 256) {
        double angle = (double)s / pow(10000.0, (double)(2*(h/2)) / (double)HH);
        pe[s*HH + h] = (h & 1) ? (float)cos(angle) : (float)sin(angle);
    }
}

__global__ void zero4_kernel(float* __restrict__ p)
{
    int idx = blockIdx.x*256 + threadIdx.x;
    ((float4*)p)[idx] = make_float4(0.f,0.f,0.f,0.f);
}

// ---------------- small row GEMM + relu into tokens ----------------
__global__ void vecmat_relu(const float* __restrict__ X, int xstride,
                            const float* __restrict__ W, int K,
                            int mode, int off, float* __restrict__ tokens)
{
    int r = blockIdx.x;
    __shared__ float xs[512];
    for (int k = threadIdx.x; k < K; k += 256) xs[k] = X[r*xstride + k];
    __syncthreads();
    int drow;
    if      (mode == 1) drow = (r>>3)*32 + ((r&7)<<1);
    else if (mode == 2) drow = (r>>3)*32 + ((r&7)<<1) + 1;
    else                drow = r*32 + off;
    int c = blockIdx.y*256 + threadIdx.x;
    float acc = 0.f;
    for (int k = 0; k < K; k++) acc = fmaf(xs[k], W[k*HH + c], acc);
    tokens[drow*HH + c] = fmaxf(acc, 0.f);
}

// ---------------- h = tokens + pe (valid rows), fused bf16 split ----------------
__global__ void addpe_kernel(const float* __restrict__ tokens,
                             const float* __restrict__ pe,
                             float* __restrict__ h,
                             __nv_bfloat16* __restrict__ hh,
                             __nv_bfloat16* __restrict__ hl, int L)
{
    int i = blockIdx.x*256 + threadIdx.x;
    float v = tokens[i];
    int srow = (i >> 10) & 31;
    if (srow < L) v += pe[srow*HH + (i & 1023)];
    h[i] = v;
    __nv_bfloat16 hi, lo; split2(v, hi, lo);
    hh[i] = hi; hl[i] = lo;
}

// ---------------- attention (one block per (b, head)), bf16-split ctx out ----------------
__global__ void attn_kernel(int L, const float* __restrict__ Q,
                            const float* __restrict__ K,
                            const float* __restrict__ V,
                            __nv_bfloat16* __restrict__ ctxh,
                            __nv_bfloat16* __restrict__ ctxl)
{
    __shared__ float Qs[32][64];
    __shared__ float KsT[64][33];
    __shared__ float Vs[32][64];
    __shared__ float P[32][33];
    int tid = threadIdx.x;
    int b = blockIdx.x >> 4, hd = blockIdx.x & 15;
    const float* qb = Q + b*SQ*HH + hd*HS;
    const float* kb = K + b*SQ*HH + hd*HS;
    const float* vb = V + b*SQ*HH + hd*HS;
    #pragma unroll
    for (int t = 0; t < 2; t++) {
        int f = tid + t*256;
        int row = f >> 4, c4 = (f & 15) << 2;
        float4 q4 = *(const float4*)(qb + row*HH + c4);
        *(float4*)&Qs[row][c4] = q4;
        float4 k4 = *(const float4*)(kb + row*HH + c4);
        KsT[c4+0][row] = k4.x; KsT[c4+1][row] = k4.y;
        KsT[c4+2][row] = k4.z; KsT[c4+3][row] = k4.w;
        float4 v4 = *(const float4*)(vb + row*HH + c4);
        *(float4*)&Vs[row][c4] = v4;
    }
    __syncthreads();
    #pragma unroll
    for (int t = 0; t < 4; t++) {
        int p = tid + t*256;
        int qr = p >> 5, kr = p & 31;
        float sc = 0.f;
        #pragma unroll
        for (int d = 0; d < 64; d++) sc = fmaf(Qs[qr][d], KsT[d][kr], sc);
        P[qr][kr] = sc * 0.125f;
    }
    __syncthreads();
    int w = tid >> 5, lane = tid & 31;
    #pragma unroll
    for (int r = 0; r < 4; r++) {
        int qr = w + r*8;
        bool vq = qr < L, vk = lane < L;
        float v = (vq && vk) ? P[qr][lane] : -1e30f;
        float mx = v;
        #pragma unroll
        for (int off = 16; off > 0; off >>= 1)
            mx = fmaxf(mx, __shfl_xor_sync(0xFFFFFFFFu, mx, off));
        float e = (vq && vk) ? expf(v - mx) : 0.f;
        float sm = e;
        #pragma unroll
        for (int off = 16; off > 0; off >>= 1)
            sm += __shfl_xor_sync(0xFFFFFFFFu, sm, off);
        P[qr][lane] = vq ? (e / sm) : 0.f;
    }
    __syncthreads();
    __nv_bfloat16* ch = ctxh + b*SQ*HH + hd*HS;
    __nv_bfloat16* cl = ctxl + b*SQ*HH + hd*HS;
    #pragma unroll
    for (int t = 0; t < 8; t++) {
        int e = tid + t*256;
        int qr = e >> 6, d = e & 63;
        float acc = 0.f;
        #pragma unroll
        for (int k = 0; k < 32; k++) acc = fmaf(P[qr][k], Vs[k][d], acc);
        __nv_bfloat16 hi, lo; split2(acc, hi, lo);
        ch[qr*HH + d] = hi;
        cl[qr*HH + d] = lo;
    }
}

// ---------------- LayerNorm(x + y) with fused bf16 split (+ optional prev copy) ----------------
__global__ void ln_kernel(const float* __restrict__ X, const float* __restrict__ Y,
                          const float* __restrict__ gam, const float* __restrict__ bet,
                          float* __restrict__ out,
                          __nv_bfloat16* __restrict__ oh, __nv_bfloat16* __restrict__ ol,
                          __nv_bfloat16* __restrict__ ph, __nv_bfloat16* __restrict__ pl)
{
    int row = blockIdx.x;
    int tid = threadIdx.x;
    const float* x = X + row*HH;
    const float* y = Y + row*HH;
    float v[4];
    float s = 0.f;
    #pragma unroll
    for (int i = 0; i < 4; i++) { v[i] = x[tid + i*256] + y[tid + i*256]; s += v[i]; }
    __shared__ float red[256];
    red[tid] = s; __syncthreads();
    for (int st = 128; st > 0; st >>= 1) {
        if (tid < st) red[tid] += red[tid + st];
        __syncthreads();
    }
    float mean = red[0] * (1.f/1024.f);
    __syncthreads();
    float q = 0.f;
    #pragma unroll
    for (int i = 0; i < 4; i++) { float d = v[i] - mean; q = fmaf(d, d, q); }
    red[tid] = q; __syncthreads();
    for (int st = 128; st > 0; st >>= 1) {
        if (tid < st) red[tid] += red[tid + st];
        __syncthreads();
    }
    float inv = rsqrtf(red[0] * (1.f/1024.f) + 1e-5f);
    #pragma unroll
    for (int i = 0; i < 4; i++) {
        int c = tid + i*256;
        float o = (v[i] - mean) * inv * gam[c] + bet[c];
        out[row*HH + c] = o;
        __nv_bfloat16 hi, lo; split2(o, hi, lo);
        oh[row*HH + c] = hi; ol[row*HH + c] = lo;
        if (ph) { ph[row*HH + c] = hi; pl[row*HH + c] = lo; }
    }
}

// ---------------- r = sigmoid(hf @ Wr) ----------------
__global__ void r_kernel(const float* __restrict__ hf, const float* __restrict__ Wr,
                         float* __restrict__ out_r, int i)
{
    int b = blockIdx.x;
    const float* x = hf + b*SQ*HH;
    float acc = 0.f;
    for (int k = threadIdx.x; k < SQ*HH; k += 256) acc = fmaf(x[k], Wr[k], acc);
    __shared__ float red[256];
    red[threadIdx.x] = acc; __syncthreads();
    for (int st = 128; st > 0; st >>= 1) {
        if (threadIdx.x < st) red[threadIdx.x] += red[threadIdx.x + st];
        __syncthreads();
    }
    if (threadIdx.x == 0) out_r[b*TACT + i] = 1.f / (1.f + expf(-red[0]));
}

// ---------------- s_new partials: [32,32768]@[32768,512], split-K 16 ----------------
__global__ void snew_kernel(const float* __restrict__ hf, const float* __restrict__ Wso,
                            float* __restrict__ spart)
{
    __shared__ float As[32][36];
    __shared__ float Bs[32][64];
    int tid = threadIdx.x;
    int n0 = blockIdx.x << 6;
    int k0 = blockIdx.y << 11;
    int col = tid & 63;
    int rg  = tid >> 6;
    int ar = tid >> 3, ac4 = (tid & 7) << 2;
    float acc[8] = {};
    for (int kc = 0; kc < 2048; kc += 32) {
        float4 av = *(const float4*)(hf + ar*(SQ*HH) + k0 + kc + ac4);
        As[ar][ac4+0] = av.x; As[ar][ac4+1] = av.y;
        As[ar][ac4+2] = av.z; As[ar][ac4+3] = av.w;
        #pragma unroll
        for (int t = 0; t < 2; t++) {
            int f = tid + t*256;
            int kk = f >> 4, c4 = (f & 15) << 2;
            *(float4*)&Bs[kk][c4] = *(const float4*)(Wso + (size_t)(k0 + kc + kk)*HIN + n0 + c4);
        }
        __syncthreads();
        #pragma unroll 8
        for (int kk = 0; kk < 32; kk++) {
            float bv = Bs[kk][col];
            #pragma unroll
            for (int r8 = 0; r8 < 8; r8++)
                acc[r8] = fmaf(As[rg*8 + r8][kk], bv, acc[r8]);
        }
        __syncthreads();
    }
    #pragma unroll
    for (int r8 = 0; r8 < 8; r8++)
        spart[blockIdx.y*(NB*HIN) + (rg*8 + r8)*HIN + n0 + col] = acc[r8];
}

__global__ void fin_kernel(const float* __restrict__ spart, float* __restrict__ srelu,
                           float* __restrict__ out_s, int i)
{
    int idx = blockIdx.x*256 + threadIdx.x;   // 16384
    float v = 0.f;
    #pragma unroll
    for (int p = 0; p < 16; p++) v += spart[p*(NB*HIN) + idx];
    v = fmaxf(v, 0.f);
    srelu[idx] = v;
    int b = idx >> 9, n = idx & 511;
    out_s[(b*TACT + i)*HIN + n] = v;
}

// ---------------- host orchestration ----------------
extern "C" void kernel_launch(void* const* d_in, const int* in_sizes, int n_in,
                              void* d_out, int out_size)
{
    const float* history_s = (const float*)d_in[0];
    const float* history_a = (const float*)d_in[1];
    const float* s_in      = (const float*)d_in[2];
    const float* a_list    = (const float*)d_in[3];
    const float* Ws        = (const float*)d_in[4];
    const float* Wa        = (const float*)d_in[5];
    const float* Wq        = (const float*)d_in[6];
    const float* Wk        = (const float*)d_in[7];
    const float* Wv        = (const float*)d_in[8];
    const float* Wo        = (const float*)d_in[9];
    const float* Wfc       = (const float*)d_in[10];
    const float* ln1_g     = (const float*)d_in[11];
    const float* ln1_b     = (const float*)d_in[12];
    const float* ln2_g     = (const float*)d_in[13];
    const float* ln2_b     = (const float*)d_in[14];
    const float* Wr        = (const float*)d_in[15];
    const float* Wso       = (const float*)d_in[16];

    float* out_r = (float*)d_out;             // [B, TA]
    float* out_s = out_r + NB*TACT;           // [B, TA, HIN]

    void* p;
    cudaGetSymbolAddress(&p, g_pe);     float* pe     = (float*)p;
    cudaGetSymbolAddress(&p, g_tokens); float* tokens = (float*)p;
    cudaGetSymbolAddress(&p, g_h);      float* h      = (float*)p;
    cudaGetSymbolAddress(&p, g_q);      float* qb     = (float*)p;
    cudaGetSymbolAddress(&p, g_kbuf);   float* kb     = (float*)p;
    cudaGetSymbolAddress(&p, g_vbuf);   float* vb     = (float*)p;
    cudaGetSymbolAddress(&p, g_tmp);    float* tmp    = (float*)p;
    cudaGetSymbolAddress(&p, g_spart);  float* spart  = (float*)p;
    cudaGetSymbolAddress(&p, g_srelu);  float* srelu  = (float*)p;
    cudaGetSymbolAddress(&p, g_hh);     __nv_bfloat16* hh   = (__nv_bfloat16*)p;
    cudaGetSymbolAddress(&p, g_hl);     __nv_bfloat16* hl   = (__nv_bfloat16*)p;
    cudaGetSymbolAddress(&p, g_ctxh);   __nv_bfloat16* ctxh = (__nv_bfloat16*)p;
    cudaGetSymbolAddress(&p, g_ctxl);   __nv_bfloat16* ctxl = (__nv_bfloat16*)p;
    cudaGetSymbolAddress(&p, g_phh);    __nv_bfloat16* phh  = (__nv_bfloat16*)p;
    cudaGetSymbolAddress(&p, g_phl);    __nv_bfloat16* phl  = (__nv_bfloat16*)p;
    cudaGetSymbolAddress(&p, g_WhT);    __nv_bfloat16* WhT  = (__nv_bfloat16*)p;
    cudaGetSymbolAddress(&p, g_WlT);    __nv_bfloat16* WlT  = (__nv_bfloat16*)p;

    cudaFuncSetAttribute(gemm_tc,  cudaFuncAttributeMaxDynamicSharedMemorySize, GEMM_SMEM);
    cudaFuncSetAttribute(gemm_qkv, cudaFuncAttributeMaxDynamicSharedMemorySize, GEMM_SMEM);

    pe_kernel<<<SQ, 256>>>(pe);
    zero4_kernel<<<TOK_ELEMS/1024, 256>>>(tokens);
    wconv_kernel<<<dim3(32, 32, 20), 256>>>(Wq, Wk, Wv, Wo, Wfc, WhT, WlT);

    vecmat_relu<<<dim3(NB*THIST, 4), 256>>>(history_s, HIN, Ws, HIN, 1, 0, tokens);
    vecmat_relu<<<dim3(NB*THIST, 4), 256>>>(history_a, AIN, Wa, AIN, 2, 0, tokens);
    vecmat_relu<<<dim3(NB, 4), 256>>>(s_in, HIN, Ws, HIN, 3, 16, tokens);

    dim3 gg(8, 16);        // N-blocks x M-blocks
    for (int i = 0; i < TACT; i++) {
        int posA = 2*THIST + 1 + 2*i;
        int L = posA + 1;
        vecmat_relu<<<dim3(NB, 4), 256>>>(a_list + i*AIN, TACT*AIN, Wa, AIN, 3, posA, tokens);
        addpe_kernel<<<TOK_ELEMS/256, 256>>>(tokens, pe, h, hh, hl, L);
        for (int j = 0; j < NLAY; j++) {
            const __nv_bfloat16* qh = (i == 0) ? hh : (phh + (size_t)j*TOK_ELEMS);
            const __nv_bfloat16* ql = (i == 0) ? hl : (phl + (size_t)j*TOK_ELEMS);
            size_t sq = (size_t)(0*4 + j)*WMAT, sk = (size_t)(1*4 + j)*WMAT;
            size_t sv = (size_t)(2*4 + j)*WMAT, so = (size_t)(3*4 + j)*WMAT;
            size_t sf = (size_t)(4*4 + j)*WMAT;
            gemm_qkv<<<dim3(8, 16, 3), 256, GEMM_SMEM>>>(qh, ql, hh, hl, WhT, WlT,
                                                          sq, sk, sv, qb, kb, vb);
            attn_kernel<<<NB*NHEAD, 256>>>(L, qb, kb, vb, ctxh, ctxl);
            gemm_tc<<<gg, 256, GEMM_SMEM>>>(ctxh, ctxl, WhT + so, WlT + so, tmp);
            ln_kernel<<<NB*SQ, 256>>>(h, tmp, ln1_g + j*HH, ln1_b + j*HH, h, hh, hl,
                                      (__nv_bfloat16*)0, (__nv_bfloat16*)0);
            gemm_tc<<<gg, 256, GEMM_SMEM>>>(hh, hl, WhT + sf, WlT + sf, tmp);
            ln_kernel<<<NB*SQ, 256>>>(h, tmp, ln2_g + j*HH, ln2_b + j*HH, h, hh, hl,
                                      phh + (size_t)j*TOK_ELEMS, phl + (size_t)j*TOK_ELEMS);
        }
        r_kernel<<<NB, 256>>>(h, Wr, out_r, i);
        snew_kernel<<<dim3(8, 16), 256>>>(h, Wso, spart);
        fin_kernel<<<64, 256>>>(spart, srelu, out_s, i);
        if (i + 1 < TACT)
            vecmat_relu<<<dim3(NB, 4), 256>>>(srelu, HIN, Ws, HIN, 3, posA + 1, tokens);
    }
}

// round 5
// speedup vs baseline: 2.7043x; 1.1277x over previous
#include <cuda_runtime.h>
#include <cuda_bf16.h>
#include <cstdint>
#include <math.h>

#define NB    32
#define SQ    32
#define HH    1024
#define NHEAD 16
#define HS    64
#define NLAY  4
#define THIST 8
#define TACT  8
#define HIN   512
#define AIN   64
#define RS    (NB*HH)          // 32768: row stride between s-positions

#define TOK_ELEMS (NB*SQ*HH)   // 1048576
#define WMAT      (HH*HH)      // 1048576

// token row layout: row = s*NB + b  (valid rows are prefix [0, 32*L))

// ---------------- scratch (device globals; no allocation) ----------------
__device__ float g_pe[SQ*HH];
__device__ float g_tokens[TOK_ELEMS];
__device__ float g_h[TOK_ELEMS];
__device__ float g_q[TOK_ELEMS];
__device__ float g_kbuf[TOK_ELEMS];
__device__ float g_vbuf[TOK_ELEMS];
__device__ float g_tmp[TOK_ELEMS];
__device__ float g_spart[32*NB*HIN];
__device__ float g_srelu[NB*HIN];
__device__ __nv_bfloat16 g_hh[TOK_ELEMS];
__device__ __nv_bfloat16 g_hl[TOK_ELEMS];
__device__ __nv_bfloat16 g_ctxh[TOK_ELEMS];
__device__ __nv_bfloat16 g_ctxl[TOK_ELEMS];
__device__ __nv_bfloat16 g_phh[NLAY*TOK_ELEMS];
__device__ __nv_bfloat16 g_phl[NLAY*TOK_ELEMS];
__device__ __nv_bfloat16 g_WhT[20*WMAT];
__device__ __nv_bfloat16 g_WlT[20*WMAT];

// ---------------- helpers ----------------
__device__ __forceinline__ uint32_t s2u(const void* p) {
    uint32_t a;
    asm("{ .reg .u64 t; cvta.to.shared.u64 t, %1; cvt.u32.u64 %0, t; }" : "=r"(a) : "l"(p));
    return a;
}

__device__ __forceinline__ void split2(float v, __nv_bfloat16& hi, __nv_bfloat16& lo) {
    hi = __float2bfloat16(v);
    lo = __float2bfloat16(v - __bfloat162float(hi));
}

#define LDM4(r, addr) \
    asm volatile("ldmatrix.sync.aligned.m8n8.x4.shared.b16 {%0,%1,%2,%3}, [%4];" \
        : "=r"((r)[0]), "=r"((r)[1]), "=r"((r)[2]), "=r"((r)[3]) : "r"(addr))

#define MMA_BF16(d, a, b0v, b1v) \
    asm volatile("mma.sync.aligned.m16n8k16.row.col.f32.bf16.bf16.f32 " \
        "{%0,%1,%2,%3}, {%4,%5,%6,%7}, {%8,%9}, {%0,%1,%2,%3};" \
        : "+f"((d)[0]), "+f"((d)[1]), "+f"((d)[2]), "+f"((d)[3]) \
        : "r"((a)[0]), "r"((a)[1]), "r"((a)[2]), "r"((a)[3]), "r"(b0v), "r"(b1v))

#define CP_ASYNC16(sa, gp) \
    asm volatile("cp.async.cg.shared.global [%0], [%1], 16;" :: "r"(sa), "l"(gp))
#define CP_COMMIT()  asm volatile("cp.async.commit_group;" ::: "memory")
#define CP_WAIT0()   asm volatile("cp.async.wait_group 0;" ::: "memory")
#define CP_WAIT1()   asm volatile("cp.async.wait_group 1;" ::: "memory")
#define CP_WAIT2()   asm volatile("cp.async.wait_group 2;" ::: "memory")

// ---------------- weight transpose + bf16 split: W[K,N] -> WT[N,K] hi/lo ----------------
__global__ void wconv_kernel(const float* __restrict__ Wq, const float* __restrict__ Wk,
                             const float* __restrict__ Wv, const float* __restrict__ Wo,
                             const float* __restrict__ Wfc,
                             __nv_bfloat16* __restrict__ WhT, __nv_bfloat16* __restrict__ WlT)
{
    int z = blockIdx.z;                 // 0..19 = type*4 + layer
    int type = z >> 2, layer = z & 3;
    const float* bases[5] = {Wq, Wk, Wv, Wo, Wfc};
    const float* W = bases[type] + (size_t)layer * WMAT;
    __shared__ float t[32][33];
    int x0 = blockIdx.x * 32;  // K
    int y0 = blockIdx.y * 32;  // N
    int tr = threadIdx.x >> 5, tc = threadIdx.x & 31;
    #pragma unroll
    for (int u = 0; u < 4; u++) {
        int r = tr + u * 8;
        t[r][tc] = W[(size_t)(x0 + r) * HH + y0 + tc];
    }
    __syncthreads();
    size_t ob = (size_t)z * WMAT;
    #pragma unroll
    for (int u = 0; u < 4; u++) {
        int r = tr + u * 8;
        float v = t[tc][r];
        __nv_bfloat16 hi, lo; split2(v, hi, lo);
        size_t off = ob + (size_t)(y0 + r) * HH + x0 + tc;
        WhT[off] = hi;
        WlT[off] = lo;
    }
}

// ---------------- bf16-split tensor-core GEMM (mma.sync) ----------------
// C[M,1024] = A[M,1024] x B^T (B stored [N,K]), M = 32*L rows.
// CTA tile 64(M) x 128(N), K-chunk 64, 4-buffer/3-outstanding cp.async pipeline.
// Stage layout (49152 B): Ah[0,8K) Al[8K,16K) Bh[16K,32K) Bl[32K,48K)
#define STAGE 49152
#define NBUF  4
#define GEMM_SMEM (NBUF*STAGE)    // 196608

__device__ __forceinline__ void issue_stage(uint32_t sbase, int buf,
    const __nv_bfloat16* __restrict__ Ah, const __nv_bfloat16* __restrict__ Al,
    const __nv_bfloat16* __restrict__ Bh, const __nv_bfloat16* __restrict__ Bl,
    int bm, int bn, int k0, int tid)
{
    uint32_t st = sbase + buf * STAGE;
    #pragma unroll
    for (int u = 0; u < 12; u++) {
        int id = tid + u * 256;
        if (id < 1024) {
            int sec = id >> 9;               // 0=Ah 1=Al
            int r = (id & 511) >> 3, c = id & 7;
            const __nv_bfloat16* gp = (sec ? Al : Ah) + (size_t)(bm + r) * HH + k0 + c * 8;
            uint32_t sa = st + sec * 8192 + r * 128 + ((c ^ (r & 7)) << 4);
            CP_ASYNC16(sa, gp);
        } else {
            int sec = (id - 1024) >> 10;     // 0=Bh 1=Bl
            int r = ((id - 1024) & 1023) >> 3, c = id & 7;
            const __nv_bfloat16* gp = (sec ? Bl : Bh) + (size_t)(bn + r) * HH + k0 + c * 8;
            uint32_t sa = st + 16384 + sec * 16384 + r * 128 + ((c ^ (r & 7)) << 4);
            CP_ASYNC16(sa, gp);
        }
    }
    CP_COMMIT();
}

__device__ __forceinline__ void gemm_body(
    const __nv_bfloat16* __restrict__ Ah, const __nv_bfloat16* __restrict__ Al,
    const __nv_bfloat16* __restrict__ Bh, const __nv_bfloat16* __restrict__ Bl,
    float* __restrict__ C)
{
    extern __shared__ char smem[];
    uint32_t sbase = s2u(smem);
    int tid = threadIdx.x, wid = tid >> 5, lane = tid & 31;
    int bm = blockIdx.y << 6, bn = blockIdx.x << 7;
    int warpM = (wid >> 2) << 5;
    int warpN = (wid & 3) << 5;

    issue_stage(sbase, 0, Ah, Al, Bh, Bl, bm, bn, 0,   tid);
    issue_stage(sbase, 1, Ah, Al, Bh, Bl, bm, bn, 64,  tid);
    issue_stage(sbase, 2, Ah, Al, Bh, Bl, bm, bn, 128, tid);

    float acc[2][4][4] = {};

    for (int s = 0; s < 16; s++) {
        if (s < 14)       { CP_WAIT2(); }
        else if (s == 14) { CP_WAIT1(); }
        else              { CP_WAIT0(); }
        __syncthreads();
        if (s + 3 < 16)
            issue_stage(sbase, (s + 3) & 3, Ah, Al, Bh, Bl, bm, bn, (s + 3) << 6, tid);
        uint32_t st = sbase + (s & 3) * STAGE;
        #pragma unroll
        for (int kk = 0; kk < 4; kk++) {
            uint32_t ah[2][4], alr[2][4];
            #pragma unroll
            for (int mt = 0; mt < 2; mt++) {
                int r = warpM + mt * 16 + (lane & 15);
                int ch = kk * 2 + (lane >> 4);
                uint32_t ad = st + r * 128 + ((ch ^ (r & 7)) << 4);
                LDM4(ah[mt], ad);
                LDM4(alr[mt], ad + 8192);
            }
            uint32_t bh[2][4], blr[2][4];
            #pragma unroll
            for (int nt = 0; nt < 2; nt++) {
                int r = warpN + nt * 16 + (lane & 7) + ((lane >> 4) << 3);
                int ch = kk * 2 + ((lane >> 3) & 1);
                uint32_t bd = st + 16384 + r * 128 + ((ch ^ (r & 7)) << 4);
                LDM4(bh[nt], bd);
                LDM4(blr[nt], bd + 16384);
            }
            #pragma unroll
            for (int mt = 0; mt < 2; mt++) {
                #pragma unroll
                for (int j = 0; j < 4; j++) {
                    uint32_t b0 = bh[j >> 1][(j & 1) * 2], b1 = bh[j >> 1][(j & 1) * 2 + 1];
                    uint32_t c0 = blr[j >> 1][(j & 1) * 2], c1 = blr[j >> 1][(j & 1) * 2 + 1];
                    MMA_BF16(acc[mt][j], ah[mt], b0, b1);
                    MMA_BF16(acc[mt][j], ah[mt], c0, c1);
                    MMA_BF16(acc[mt][j], alr[mt], b0, b1);
                }
            }
        }
    }

    #pragma unroll
    for (int mt = 0; mt < 2; mt++) {
        int row = bm + warpM + mt * 16 + (lane >> 2);
        #pragma unroll
        for (int j = 0; j < 4; j++) {
            int col = bn + warpN + j * 8 + ((lane & 3) << 1);
            *(float2*)&C[(size_t)row * HH + col] =
                make_float2(acc[mt][j][0], acc[mt][j][1]);
            *(float2*)&C[(size_t)(row + 8) * HH + col] =
                make_float2(acc[mt][j][2], acc[mt][j][3]);
        }
    }
}

__global__ void __launch_bounds__(256, 1) gemm_tc(
    const __nv_bfloat16* __restrict__ Ah, const __nv_bfloat16* __restrict__ Al,
    const __nv_bfloat16* __restrict__ Bh, const __nv_bfloat16* __restrict__ Bl,
    float* __restrict__ C)
{
    gemm_body(Ah, Al, Bh, Bl, C);
}

__global__ void __launch_bounds__(256, 1) gemm_qkv(
    const __nv_bfloat16* __restrict__ qh, const __nv_bfloat16* __restrict__ ql,
    const __nv_bfloat16* __restrict__ hh, const __nv_bfloat16* __restrict__ hl,
    const __nv_bfloat16* __restrict__ WhT, const __nv_bfloat16* __restrict__ WlT,
    size_t sq, size_t sk, size_t sv,
    float* __restrict__ Q, float* __restrict__ K, float* __restrict__ V)
{
    int z = blockIdx.z;
    const __nv_bfloat16* Ah = (z == 2) ? hh : qh;
    const __nv_bfloat16* Al = (z == 2) ? hl : ql;
    size_t off = (z == 0) ? sq : (z == 1) ? sk : sv;
    float* C = (z == 0) ? Q : (z == 1) ? K : V;
    gemm_body(Ah, Al, WhT + off, WlT + off, C);
}

// ---------------- positional encoding (float) ----------------
__global__ void pe_kernel(float* __restrict__ pe)
{
    int s = blockIdx.x;
    for (int h = threadIdx.x; h < HH; h += 256) {
        float e = (float)(2 * (h / 2)) * (1.0f / HH);
        float freq = exp2f(-e * 13.287712379549449f);   // log2(10000)
        float angle = (float)s * freq;
        pe[s*HH + h] = (h & 1) ? cosf(angle) : sinf(angle);
    }
}

__global__ void zero4_kernel(float* __restrict__ p)
{
    int idx = blockIdx.x*256 + threadIdx.x;
    ((float4*)p)[idx] = make_float4(0.f,0.f,0.f,0.f);
}

// zero stale prev rows [r0, r0+64) for all layers, both hi/lo buffers
__global__ void zero_prev_kernel(__nv_bfloat16* __restrict__ ph,
                                 __nv_bfloat16* __restrict__ pl, int r0)
{
    int idx = blockIdx.x*256 + threadIdx.x;       // 4 layers * 8192 uint4
    int j = idx >> 13;
    int w = idx & 8191;
    size_t off = (size_t)j*TOK_ELEMS + (size_t)r0*HH;
    ((uint4*)(ph + off))[w] = make_uint4(0,0,0,0);
    ((uint4*)(pl + off))[w] = make_uint4(0,0,0,0);
}

// ---------------- small row GEMM + relu into tokens ([s][b] layout) ----------------
__global__ void vecmat_relu(const float* __restrict__ X, int xstride,
                            const float* __restrict__ W, int K,
                            int mode, int off, float* __restrict__ tokens)
{
    int r = blockIdx.x;
    __shared__ float xs[512];
    for (int k = threadIdx.x; k < K; k += 256) xs[k] = X[r*xstride + k];
    __syncthreads();
    int drow;
    if      (mode == 1) drow = (2*(r&7))*NB + (r>>3);
    else if (mode == 2) drow = (2*(r&7)+1)*NB + (r>>3);
    else                drow = off*NB + r;
    int c = blockIdx.y*256 + threadIdx.x;
    float acc = 0.f;
    for (int k = 0; k < K; k++) acc = fmaf(xs[k], W[k*HH + c], acc);
    tokens[drow*HH + c] = fmaxf(acc, 0.f);
}

// ---------------- h = tokens + pe (valid rows), fused bf16 split ----------------
__global__ void addpe_kernel(const float* __restrict__ tokens,
                             const float* __restrict__ pe,
                             float* __restrict__ h,
                             __nv_bfloat16* __restrict__ hh,
                             __nv_bfloat16* __restrict__ hl, int L)
{
    int i = blockIdx.x*256 + threadIdx.x;
    float v = tokens[i];
    int srow = i >> 15;                       // s index ([s][b] layout)
    if (srow < L) v += pe[srow*HH + (i & 1023)];
    h[i] = v;
    __nv_bfloat16 hi, lo; split2(v, hi, lo);
    hh[i] = hi; hl[i] = lo;
}

// ---------------- attention (one block per (b, head)), [s][b] layout ----------------
__global__ void attn_kernel(int L, const float* __restrict__ Q,
                            const float* __restrict__ K,
                            const float* __restrict__ V,
                            __nv_bfloat16* __restrict__ ctxh,
                            __nv_bfloat16* __restrict__ ctxl)
{
    __shared__ float Qs[32][64];
    __shared__ float KsT[64][33];
    __shared__ float Vs[32][64];
    __shared__ float P[32][33];
    int tid = threadIdx.x;
    int b = blockIdx.x >> 4, hd = blockIdx.x & 15;
    const float* qb = Q + b*HH + hd*HS;
    const float* kb = K + b*HH + hd*HS;
    const float* vb = V + b*HH + hd*HS;
    #pragma unroll
    for (int t = 0; t < 2; t++) {
        int f = tid + t*256;
        int row = f >> 4, c4 = (f & 15) << 2;
        float4 q4 = *(const float4*)(qb + row*RS + c4);
        *(float4*)&Qs[row][c4] = q4;
        float4 k4 = *(const float4*)(kb + row*RS + c4);
        KsT[c4+0][row] = k4.x; KsT[c4+1][row] = k4.y;
        KsT[c4+2][row] = k4.z; KsT[c4+3][row] = k4.w;
        float4 v4 = *(const float4*)(vb + row*RS + c4);
        *(float4*)&Vs[row][c4] = v4;
    }
    __syncthreads();
    #pragma unroll
    for (int t = 0; t < 4; t++) {
        int p = tid + t*256;
        int qr = p >> 5, kr = p & 31;
        float sc = 0.f;
        #pragma unroll
        for (int d = 0; d < 64; d++) sc = fmaf(Qs[qr][d], KsT[d][kr], sc);
        P[qr][kr] = sc * 0.125f;
    }
    __syncthreads();
    int w = tid >> 5, lane = tid & 31;
    #pragma unroll
    for (int r = 0; r < 4; r++) {
        int qr = w + r*8;
        bool vq = qr < L, vk = lane < L;
        float v = (vq && vk) ? P[qr][lane] : -1e30f;
        float mx = v;
        #pragma unroll
        for (int off = 16; off > 0; off >>= 1)
            mx = fmaxf(mx, __shfl_xor_sync(0xFFFFFFFFu, mx, off));
        float e = (vq && vk) ? expf(v - mx) : 0.f;
        float sm = e;
        #pragma unroll
        for (int off = 16; off > 0; off >>= 1)
            sm += __shfl_xor_sync(0xFFFFFFFFu, sm, off);
        P[qr][lane] = vq ? (e / sm) : 0.f;
    }
    __syncthreads();
    __nv_bfloat16* ch = ctxh + b*HH + hd*HS;
    __nv_bfloat16* cl = ctxl + b*HH + hd*HS;
    #pragma unroll
    for (int t = 0; t < 8; t++) {
        int e = tid + t*256;
        int qr = e >> 6, d = e & 63;
        float acc = 0.f;
        #pragma unroll
        for (int k = 0; k < 32; k++) acc = fmaf(P[qr][k], Vs[k][d], acc);
        __nv_bfloat16 hi, lo; split2(acc, hi, lo);
        ch[qr*RS + d] = hi;
        cl[qr*RS + d] = lo;
    }
}

// ---------------- LayerNorm(x + y), shuffle reductions, fused split ----------------
__global__ void ln_kernel(const float* __restrict__ X, const float* __restrict__ Y,
                          const float* __restrict__ gam, const float* __restrict__ bet,
                          float* __restrict__ out,
                          __nv_bfloat16* __restrict__ oh, __nv_bfloat16* __restrict__ ol,
                          __nv_bfloat16* __restrict__ ph, __nv_bfloat16* __restrict__ pl)
{
    int row = blockIdx.x;
    int tid = threadIdx.x, wid = tid >> 5, lane = tid & 31;
    const float* x = X + row*HH;
    const float* y = Y + row*HH;
    float v[4];
    float s = 0.f;
    #pragma unroll
    for (int i = 0; i < 4; i++) { v[i] = x[tid + i*256] + y[tid + i*256]; s += v[i]; }
    #pragma unroll
    for (int off = 16; off > 0; off >>= 1) s += __shfl_xor_sync(0xFFFFFFFFu, s, off);
    __shared__ float red[8], red2[8];
    if (lane == 0) red[wid] = s;
    __syncthreads();
    float tot = 0.f;
    #pragma unroll
    for (int wdx = 0; wdx < 8; wdx++) tot += red[wdx];
    float mean = tot * (1.f/1024.f);
    float q = 0.f;
    #pragma unroll
    for (int i = 0; i < 4; i++) { float d = v[i] - mean; q = fmaf(d, d, q); }
    #pragma unroll
    for (int off = 16; off > 0; off >>= 1) q += __shfl_xor_sync(0xFFFFFFFFu, q, off);
    if (lane == 0) red2[wid] = q;
    __syncthreads();
    float tq = 0.f;
    #pragma unroll
    for (int wdx = 0; wdx < 8; wdx++) tq += red2[wdx];
    float inv = rsqrtf(tq * (1.f/1024.f) + 1e-5f);
    #pragma unroll
    for (int i = 0; i < 4; i++) {
        int c = tid + i*256;
        float o = (v[i] - mean) * inv * gam[c] + bet[c];
        out[row*HH + c] = o;
        __nv_bfloat16 hi, lo; split2(o, hi, lo);
        oh[row*HH + c] = hi; ol[row*HH + c] = lo;
        if (ph) { ph[row*HH + c] = hi; pl[row*HH + c] = lo; }
    }
}

// ---------------- r = sigmoid(hf @ Wr), [s][b] layout ----------------
__global__ void r_kernel(const float* __restrict__ h, const float* __restrict__ Wr,
                         float* __restrict__ out_r, int i)
{
    int b = blockIdx.x;
    int tid = threadIdx.x, wid = tid >> 5, lane = tid & 31;
    float acc = 0.f;
    for (int k = tid; k < SQ*HH; k += 256) {
        int s = k >> 10;
        acc = fmaf(h[s*RS + b*HH + (k & 1023)], Wr[k], acc);
    }
    #pragma unroll
    for (int off = 16; off > 0; off >>= 1) acc += __shfl_xor_sync(0xFFFFFFFFu, acc, off);
    __shared__ float red[8];
    if (lane == 0) red[wid] = acc;
    __syncthreads();
    if (tid == 0) {
        float t = 0.f;
        #pragma unroll
        for (int wdx = 0; wdx < 8; wdx++) t += red[wdx];
        out_r[b*TACT + i] = 1.f / (1.f + expf(-t));
    }
}

// ---------------- s_new partials: [32,32768]@[32768,512], split-K 32 ----------------
__global__ void snew_kernel(const float* __restrict__ h, const float* __restrict__ Wso,
                            float* __restrict__ spart)
{
    __shared__ float As[32][36];
    __shared__ float Bs[32][64];
    int tid = threadIdx.x;
    int n0 = blockIdx.x << 6;
    int k0 = blockIdx.y << 10;      // 1024-wide K slice = one s-position
    int sblk = blockIdx.y;
    int col = tid & 63;
    int rg  = tid >> 6;
    int ar = tid >> 3, ac4 = (tid & 7) << 2;
    float acc[8] = {};
    for (int kc = 0; kc < 1024; kc += 32) {
        // A[b=ar][k] at h[sblk*RS + ar*HH + (kc+ac4)]
        float4 av = *(const float4*)(h + sblk*RS + ar*HH + kc + ac4);
        As[ar][ac4+0] = av.x; As[ar][ac4+1] = av.y;
        As[ar][ac4+2] = av.z; As[ar][ac4+3] = av.w;
        #pragma unroll
        for (int t = 0; t < 2; t++) {
            int f = tid + t*256;
            int kk = f >> 4, c4 = (f & 15) << 2;
            *(float4*)&Bs[kk][c4] = *(const float4*)(Wso + (size_t)(k0 + kc + kk)*HIN + n0 + c4);
        }
        __syncthreads();
        #pragma unroll 8
        for (int kk = 0; kk < 32; kk++) {
            float bv = Bs[kk][col];
            #pragma unroll
            for (int r8 = 0; r8 < 8; r8++)
                acc[r8] = fmaf(As[rg*8 + r8][kk], bv, acc[r8]);
        }
        __syncthreads();
    }
    #pragma unroll
    for (int r8 = 0; r8 < 8; r8++)
        spart[blockIdx.y*(NB*HIN) + (rg*8 + r8)*HIN + n0 + col] = acc[r8];
}

__global__ void fin_kernel(const float* __restrict__ spart, float* __restrict__ srelu,
                           float* __restrict__ out_s, int i)
{
    int idx = blockIdx.x*256 + threadIdx.x;   // 16384
    float v = 0.f;
    #pragma unroll
    for (int p = 0; p < 32; p++) v += spart[p*(NB*HIN) + idx];
    v = fmaxf(v, 0.f);
    srelu[idx] = v;
    int b = idx >> 9, n = idx & 511;
    out_s[(b*TACT + i)*HIN + n] = v;
}

// ---------------- host orchestration ----------------
extern "C" void kernel_launch(void* const* d_in, const int* in_sizes, int n_in,
                              void* d_out, int out_size)
{
    const float* history_s = (const float*)d_in[0];
    const float* history_a = (const float*)d_in[1];
    const float* s_in      = (const float*)d_in[2];
    const float* a_list    = (const float*)d_in[3];
    const float* Ws        = (const float*)d_in[4];
    const float* Wa        = (const float*)d_in[5];
    const float* Wq        = (const float*)d_in[6];
    const float* Wk        = (const float*)d_in[7];
    const float* Wv        = (const float*)d_in[8];
    const float* Wo        = (const float*)d_in[9];
    const float* Wfc       = (const float*)d_in[10];
    const float* ln1_g     = (const float*)d_in[11];
    const float* ln1_b     = (const float*)d_in[12];
    const float* ln2_g     = (const float*)d_in[13];
    const float* ln2_b     = (const float*)d_in[14];
    const float* Wr        = (const float*)d_in[15];
    const float* Wso       = (const float*)d_in[16];

    float* out_r = (float*)d_out;             // [B, TA]
    float* out_s = out_r + NB*TACT;           // [B, TA, HIN]

    void* p;
    cudaGetSymbolAddress(&p, g_pe);     float* pe     = (float*)p;
    cudaGetSymbolAddress(&p, g_tokens); float* tokens = (float*)p;
    cudaGetSymbolAddress(&p, g_h);      float* h      = (float*)p;
    cudaGetSymbolAddress(&p, g_q);      float* qb     = (float*)p;
    cudaGetSymbolAddress(&p, g_kbuf);   float* kb     = (float*)p;
    cudaGetSymbolAddress(&p, g_vbuf);   float* vb     = (float*)p;
    cudaGetSymbolAddress(&p, g_tmp);    float* tmp    = (float*)p;
    cudaGetSymbolAddress(&p, g_spart);  float* spart  = (float*)p;
    cudaGetSymbolAddress(&p, g_srelu);  float* srelu  = (float*)p;
    cudaGetSymbolAddress(&p, g_hh);     __nv_bfloat16* hh   = (__nv_bfloat16*)p;
    cudaGetSymbolAddress(&p, g_hl);     __nv_bfloat16* hl   = (__nv_bfloat16*)p;
    cudaGetSymbolAddress(&p, g_ctxh);   __nv_bfloat16* ctxh = (__nv_bfloat16*)p;
    cudaGetSymbolAddress(&p, g_ctxl);   __nv_bfloat16* ctxl = (__nv_bfloat16*)p;
    cudaGetSymbolAddress(&p, g_phh);    __nv_bfloat16* phh  = (__nv_bfloat16*)p;
    cudaGetSymbolAddress(&p, g_phl);    __nv_bfloat16* phl  = (__nv_bfloat16*)p;
    cudaGetSymbolAddress(&p, g_WhT);    __nv_bfloat16* WhT  = (__nv_bfloat16*)p;
    cudaGetSymbolAddress(&p, g_WlT);    __nv_bfloat16* WlT  = (__nv_bfloat16*)p;

    cudaFuncSetAttribute(gemm_tc,  cudaFuncAttributeMaxDynamicSharedMemorySize, GEMM_SMEM);
    cudaFuncSetAttribute(gemm_qkv, cudaFuncAttributeMaxDynamicSharedMemorySize, GEMM_SMEM);

    pe_kernel<<<SQ, 256>>>(pe);
    zero4_kernel<<<TOK_ELEMS/1024, 256>>>(tokens);
    wconv_kernel<<<dim3(32, 32, 20), 256>>>(Wq, Wk, Wv, Wo, Wfc, WhT, WlT);

    vecmat_relu<<<dim3(NB*THIST, 4), 256>>>(history_s, HIN, Ws, HIN, 1, 0, tokens);
    vecmat_relu<<<dim3(NB*THIST, 4), 256>>>(history_a, AIN, Wa, AIN, 2, 0, tokens);
    vecmat_relu<<<dim3(NB, 4), 256>>>(s_in, HIN, Ws, HIN, 3, 16, tokens);

    for (int i = 0; i < TACT; i++) {
        int posA = 2*THIST + 1 + 2*i;
        int L = posA + 1;
        int M = NB * L;                 // valid rows (prefix), divisible by 64
        int Mt = M >> 6;                // M-tiles
        vecmat_relu<<<dim3(NB, 4), 256>>>(a_list + i*AIN, TACT*AIN, Wa, AIN, 3, posA, tokens);
        addpe_kernel<<<TOK_ELEMS/256, 256>>>(tokens, pe, h, hh, hl, L);
        if (i > 0)
            zero_prev_kernel<<<128, 256>>>(phh, phl, M - 2*NB);
        for (int j = 0; j < NLAY; j++) {
            const __nv_bfloat16* qh = (i == 0) ? hh : (phh + (size_t)j*TOK_ELEMS);
            const __nv_bfloat16* ql = (i == 0) ? hl : (phl + (size_t)j*TOK_ELEMS);
            size_t sq = (size_t)(0*4 + j)*WMAT, sk = (size_t)(1*4 + j)*WMAT;
            size_t sv = (size_t)(2*4 + j)*WMAT, so = (size_t)(3*4 + j)*WMAT;
            size_t sf = (size_t)(4*4 + j)*WMAT;
            gemm_qkv<<<dim3(8, Mt, 3), 256, GEMM_SMEM>>>(qh, ql, hh, hl, WhT, WlT,
                                                          sq, sk, sv, qb, kb, vb);
            attn_kernel<<<NB*NHEAD, 256>>>(L, qb, kb, vb, ctxh, ctxl);
            gemm_tc<<<dim3(8, Mt), 256, GEMM_SMEM>>>(ctxh, ctxl, WhT + so, WlT + so, tmp);
            ln_kernel<<<M, 256>>>(h, tmp, ln1_g + j*HH, ln1_b + j*HH, h, hh, hl,
                                  (__nv_bfloat16*)0, (__nv_bfloat16*)0);
            gemm_tc<<<dim3(8, Mt), 256, GEMM_SMEM>>>(hh, hl, WhT + sf, WlT + sf, tmp);
            ln_kernel<<<M, 256>>>(h, tmp, ln2_g + j*HH, ln2_b + j*HH, h, hh, hl,
                                  phh + (size_t)j*TOK_ELEMS, phl + (size_t)j*TOK_ELEMS);
        }
        r_kernel<<<NB, 256>>>(h, Wr, out_r, i);
        snew_kernel<<<dim3(8, 32), 256>>>(h, Wso, spart);
        fin_kernel<<<64, 256>>>(spart, srelu, out_s, i);
        if (i + 1 < TACT)
            vecmat_relu<<<dim3(NB, 4), 256>>>(srelu, HIN, Ws, HIN, 3, posA + 1, tokens);
    }
}

// round 6
// speedup vs baseline: 2.7279x; 1.0087x over previous
#include <cuda_runtime.h>
#include <cuda_bf16.h>
#include <cstdint>
#include <math.h>

#define NB    32
#define SQ    32
#define HH    1024
#define NHEAD 16
#define HS    64
#define NLAY  4
#define THIST 8
#define TACT  8
#define HIN   512
#define AIN   64
#define RS    (NB*HH)          // 32768: row stride between s-positions

#define TOK_ELEMS (NB*SQ*HH)   // 1048576
#define WMAT      (HH*HH)      // 1048576

// token row layout: row = s*NB + b  (valid rows are prefix [0, 32*L))

// ---------------- scratch (device globals; no allocation) ----------------
__device__ float g_pe[SQ*HH];
__device__ float g_tokens[TOK_ELEMS];
__device__ float g_h[TOK_ELEMS];
__device__ float g_qbuf[NLAY*TOK_ELEMS];   // per-layer Q
__device__ float g_kbig[NLAY*TOK_ELEMS];   // per-layer K
__device__ float g_vbuf[TOK_ELEMS];
__device__ float g_tmp[TOK_ELEMS];
__device__ float g_spart[32*NB*HIN];
__device__ float g_srelu[NB*HIN];
__device__ __nv_bfloat16 g_hh[TOK_ELEMS];
__device__ __nv_bfloat16 g_hl[TOK_ELEMS];
__device__ __nv_bfloat16 g_ctxh[TOK_ELEMS];
__device__ __nv_bfloat16 g_ctxl[TOK_ELEMS];
__device__ __nv_bfloat16 g_phh[NLAY*TOK_ELEMS];
__device__ __nv_bfloat16 g_phl[NLAY*TOK_ELEMS];
__device__ __nv_bfloat16 g_WhT[20*WMAT];
__device__ __nv_bfloat16 g_WlT[20*WMAT];

// ---------------- helpers ----------------
__device__ __forceinline__ uint32_t s2u(const void* p) {
    uint32_t a;
    asm("{ .reg .u64 t; cvta.to.shared.u64 t, %1; cvt.u32.u64 %0, t; }" : "=r"(a) : "l"(p));
    return a;
}

__device__ __forceinline__ void split2(float v, __nv_bfloat16& hi, __nv_bfloat16& lo) {
    hi = __float2bfloat16(v);
    lo = __float2bfloat16(v - __bfloat162float(hi));
}

#define LDM4(r, addr) \
    asm volatile("ldmatrix.sync.aligned.m8n8.x4.shared.b16 {%0,%1,%2,%3}, [%4];" \
        : "=r"((r)[0]), "=r"((r)[1]), "=r"((r)[2]), "=r"((r)[3]) : "r"(addr))

#define MMA_BF16(d, a, b0v, b1v) \
    asm volatile("mma.sync.aligned.m16n8k16.row.col.f32.bf16.bf16.f32 " \
        "{%0,%1,%2,%3}, {%4,%5,%6,%7}, {%8,%9}, {%0,%1,%2,%3};" \
        : "+f"((d)[0]), "+f"((d)[1]), "+f"((d)[2]), "+f"((d)[3]) \
        : "r"((a)[0]), "r"((a)[1]), "r"((a)[2]), "r"((a)[3]), "r"(b0v), "r"(b1v))

#define CP_ASYNC16(sa, gp) \
    asm volatile("cp.async.cg.shared.global [%0], [%1], 16;" :: "r"(sa), "l"(gp))
#define CP_ASYNC16Z(sa, gp, sz) \
    asm volatile("cp.async.cg.shared.global [%0], [%1], 16, %2;" :: "r"(sa), "l"(gp), "r"(sz))
#define CP_COMMIT()  asm volatile("cp.async.commit_group;" ::: "memory")
#define CP_WAIT0()   asm volatile("cp.async.wait_group 0;" ::: "memory")
#define CP_WAIT1()   asm volatile("cp.async.wait_group 1;" ::: "memory")
#define CP_WAIT2()   asm volatile("cp.async.wait_group 2;" ::: "memory")

// ---------------- weight transpose + bf16 split: W[K,N] -> WT[N,K] hi/lo ----------------
__global__ void wconv_kernel(const float* __restrict__ Wq, const float* __restrict__ Wk,
                             const float* __restrict__ Wv, const float* __restrict__ Wo,
                             const float* __restrict__ Wfc,
                             __nv_bfloat16* __restrict__ WhT, __nv_bfloat16* __restrict__ WlT)
{
    int z = blockIdx.z;                 // 0..19 = type*4 + layer
    int type = z >> 2, layer = z & 3;
    const float* bases[5] = {Wq, Wk, Wv, Wo, Wfc};
    const float* W = bases[type] + (size_t)layer * WMAT;
    __shared__ float t[32][33];
    int x0 = blockIdx.x * 32;  // K
    int y0 = blockIdx.y * 32;  // N
    int tr = threadIdx.x >> 5, tc = threadIdx.x & 31;
    #pragma unroll
    for (int u = 0; u < 4; u++) {
        int r = tr + u * 8;
        t[r][tc] = W[(size_t)(x0 + r) * HH + y0 + tc];
    }
    __syncthreads();
    size_t ob = (size_t)z * WMAT;
    #pragma unroll
    for (int u = 0; u < 4; u++) {
        int r = tr + u * 8;
        float v = t[tc][r];
        __nv_bfloat16 hi, lo; split2(v, hi, lo);
        size_t off = ob + (size_t)(y0 + r) * HH + x0 + tc;
        WhT[off] = hi;
        WlT[off] = lo;
    }
}

// ---------------- bf16-split tensor-core GEMM (mma.sync) ----------------
// C[M,1024] = A[M,1024] x B^T (B stored [N,K]).  A rows >= mvalid read as zero.
// CTA tile 64(M) x 128(N), K-chunk 64, 4-buffer/3-outstanding cp.async pipeline.
#define STAGE 49152
#define NBUF  4
#define GEMM_SMEM (NBUF*STAGE)    // 196608

__device__ __forceinline__ void issue_stage(uint32_t sbase, int buf,
    const __nv_bfloat16* __restrict__ Ah, const __nv_bfloat16* __restrict__ Al,
    const __nv_bfloat16* __restrict__ Bh, const __nv_bfloat16* __restrict__ Bl,
    int bm, int bn, int k0, int tid, int mvalid)
{
    uint32_t st = sbase + buf * STAGE;
    #pragma unroll
    for (int u = 0; u < 12; u++) {
        int id = tid + u * 256;
        if (id < 1024) {
            int sec = id >> 9;               // 0=Ah 1=Al
            int r = (id & 511) >> 3, c = id & 7;
            const __nv_bfloat16* gp = (sec ? Al : Ah) + (size_t)(bm + r) * HH + k0 + c * 8;
            uint32_t sa = st + sec * 8192 + r * 128 + ((c ^ (r & 7)) << 4);
            uint32_t sz = ((bm + r) < mvalid) ? 16u : 0u;
            CP_ASYNC16Z(sa, gp, sz);
        } else {
            int sec = (id - 1024) >> 10;     // 0=Bh 1=Bl
            int r = ((id - 1024) & 1023) >> 3, c = id & 7;
            const __nv_bfloat16* gp = (sec ? Bl : Bh) + (size_t)(bn + r) * HH + k0 + c * 8;
            uint32_t sa = st + 16384 + sec * 16384 + r * 128 + ((c ^ (r & 7)) << 4);
            CP_ASYNC16(sa, gp);
        }
    }
    CP_COMMIT();
}

__device__ __forceinline__ void gemm_body(
    const __nv_bfloat16* __restrict__ Ah, const __nv_bfloat16* __restrict__ Al,
    const __nv_bfloat16* __restrict__ Bh, const __nv_bfloat16* __restrict__ Bl,
    float* __restrict__ C, int mvalid)
{
    extern __shared__ char smem[];
    uint32_t sbase = s2u(smem);
    int tid = threadIdx.x, wid = tid >> 5, lane = tid & 31;
    int bm = blockIdx.y << 6, bn = blockIdx.x << 7;
    int warpM = (wid >> 2) << 5;
    int warpN = (wid & 3) << 5;

    issue_stage(sbase, 0, Ah, Al, Bh, Bl, bm, bn, 0,   tid, mvalid);
    issue_stage(sbase, 1, Ah, Al, Bh, Bl, bm, bn, 64,  tid, mvalid);
    issue_stage(sbase, 2, Ah, Al, Bh, Bl, bm, bn, 128, tid, mvalid);

    float acc[2][4][4] = {};

    for (int s = 0; s < 16; s++) {
        if (s < 14)       { CP_WAIT2(); }
        else if (s == 14) { CP_WAIT1(); }
        else              { CP_WAIT0(); }
        __syncthreads();
        if (s + 3 < 16)
            issue_stage(sbase, (s + 3) & 3, Ah, Al, Bh, Bl, bm, bn, (s + 3) << 6, tid, mvalid);
        uint32_t st = sbase + (s & 3) * STAGE;
        #pragma unroll
        for (int kk = 0; kk < 4; kk++) {
            uint32_t ah[2][4], alr[2][4];
            #pragma unroll
            for (int mt = 0; mt < 2; mt++) {
                int r = warpM + mt * 16 + (lane & 15);
                int ch = kk * 2 + (lane >> 4);
                uint32_t ad = st + r * 128 + ((ch ^ (r & 7)) << 4);
                LDM4(ah[mt], ad);
                LDM4(alr[mt], ad + 8192);
            }
            uint32_t bh[2][4], blr[2][4];
            #pragma unroll
            for (int nt = 0; nt < 2; nt++) {
                int r = warpN + nt * 16 + (lane & 7) + ((lane >> 4) << 3);
                int ch = kk * 2 + ((lane >> 3) & 1);
                uint32_t bd = st + 16384 + r * 128 + ((ch ^ (r & 7)) << 4);
                LDM4(bh[nt], bd);
                LDM4(blr[nt], bd + 16384);
            }
            #pragma unroll
            for (int mt = 0; mt < 2; mt++) {
                #pragma unroll
                for (int j = 0; j < 4; j++) {
                    uint32_t b0 = bh[j >> 1][(j & 1) * 2], b1 = bh[j >> 1][(j & 1) * 2 + 1];
                    uint32_t c0 = blr[j >> 1][(j & 1) * 2], c1 = blr[j >> 1][(j & 1) * 2 + 1];
                    MMA_BF16(acc[mt][j], ah[mt], b0, b1);
                    MMA_BF16(acc[mt][j], ah[mt], c0, c1);
                    MMA_BF16(acc[mt][j], alr[mt], b0, b1);
                }
            }
        }
    }

    #pragma unroll
    for (int mt = 0; mt < 2; mt++) {
        int row = bm + warpM + mt * 16 + (lane >> 2);
        #pragma unroll
        for (int j = 0; j < 4; j++) {
            int col = bn + warpN + j * 8 + ((lane & 3) << 1);
            *(float2*)&C[(size_t)row * HH + col] =
                make_float2(acc[mt][j][0], acc[mt][j][1]);
            *(float2*)&C[(size_t)(row + 8) * HH + col] =
                make_float2(acc[mt][j][2], acc[mt][j][3]);
        }
    }
}

__global__ void __launch_bounds__(256, 1) gemm_tc(
    const __nv_bfloat16* __restrict__ Ah, const __nv_bfloat16* __restrict__ Al,
    const __nv_bfloat16* __restrict__ Bh, const __nv_bfloat16* __restrict__ Bl,
    float* __restrict__ C, int mvalid)
{
    gemm_body(Ah, Al, Bh, Bl, C, mvalid);
}

// step-0 QKV: all operands from current hh
__global__ void __launch_bounds__(256, 1) gemm_qkv3(
    const __nv_bfloat16* __restrict__ hh, const __nv_bfloat16* __restrict__ hl,
    const __nv_bfloat16* __restrict__ WhT, const __nv_bfloat16* __restrict__ WlT,
    size_t sq, size_t sk, size_t sv,
    float* __restrict__ Q, float* __restrict__ K, float* __restrict__ V, int mvalid)
{
    int z = blockIdx.z;
    size_t off = (z == 0) ? sq : (z == 1) ? sk : sv;
    float* C = (z == 0) ? Q : (z == 1) ? K : V;
    gemm_body(hh, hl, WhT + off, WlT + off, C, mvalid);
}

// look-ahead Q,K for next step from prev_h[j]
__global__ void __launch_bounds__(256, 1) gemm_qk(
    const __nv_bfloat16* __restrict__ ph, const __nv_bfloat16* __restrict__ pl,
    const __nv_bfloat16* __restrict__ WhT, const __nv_bfloat16* __restrict__ WlT,
    size_t sq, size_t sk,
    float* __restrict__ Q, float* __restrict__ K, int mvalid)
{
    int z = blockIdx.z;
    size_t off = (z == 0) ? sq : sk;
    float* C = (z == 0) ? Q : K;
    gemm_body(ph, pl, WhT + off, WlT + off, C, mvalid);
}

// ---------------- positional encoding ----------------
__global__ void pe_kernel(float* __restrict__ pe)
{
    int s = blockIdx.x;
    for (int h = threadIdx.x; h < HH; h += 256) {
        float e = (float)(2 * (h / 2)) * (1.0f / HH);
        float freq = exp2f(-e * 13.287712379549449f);   // log2(10000)
        float angle = (float)s * freq;
        pe[s*HH + h] = (h & 1) ? cosf(angle) : sinf(angle);
    }
}

__global__ void zero4_kernel(float* __restrict__ p)
{
    int idx = blockIdx.x*256 + threadIdx.x;
    ((float4*)p)[idx] = make_float4(0.f,0.f,0.f,0.f);
}

// ---------------- small row GEMM + relu into tokens ([s][b] layout) ----------------
__global__ void vecmat_relu(const float* __restrict__ X, int xstride,
                            const float* __restrict__ W, int K,
                            int mode, int off, float* __restrict__ tokens)
{
    int r = blockIdx.x;
    __shared__ float xs[512];
    for (int k = threadIdx.x; k < K; k += 256) xs[k] = X[r*xstride + k];
    __syncthreads();
    int drow;
    if      (mode == 1) drow = (2*(r&7))*NB + (r>>3);
    else if (mode == 2) drow = (2*(r&7)+1)*NB + (r>>3);
    else                drow = off*NB + r;
    int c = blockIdx.y*256 + threadIdx.x;
    float acc = 0.f;
    for (int k = 0; k < K; k++) acc = fmaf(xs[k], W[k*HH + c], acc);
    tokens[drow*HH + c] = fmaxf(acc, 0.f);
}

// ---------------- h = tokens + pe (valid rows), fused bf16 split ----------------
__global__ void addpe_kernel(const float* __restrict__ tokens,
                             const float* __restrict__ pe,
                             float* __restrict__ h,
                             __nv_bfloat16* __restrict__ hh,
                             __nv_bfloat16* __restrict__ hl, int L)
{
    int i = blockIdx.x*256 + threadIdx.x;
    float v = tokens[i];
    int srow = i >> 15;                       // s index ([s][b] layout)
    if (srow < L) v += pe[srow*HH + (i & 1023)];
    h[i] = v;
    __nv_bfloat16 hi, lo; split2(v, hi, lo);
    hh[i] = hi; hl[i] = lo;
}

// ---------------- attention (one block per (b, head)), [s][b] layout ----------------
__global__ void attn_kernel(int L, const float* __restrict__ Q,
                            const float* __restrict__ K,
                            const float* __restrict__ V,
                            __nv_bfloat16* __restrict__ ctxh,
                            __nv_bfloat16* __restrict__ ctxl)
{
    __shared__ float Qs[32][64];
    __shared__ float KsT[64][33];
    __shared__ float Vs[32][64];
    __shared__ float P[32][33];
    int tid = threadIdx.x;
    int b = blockIdx.x >> 4, hd = blockIdx.x & 15;
    const float* qb = Q + b*HH + hd*HS;
    const float* kb = K + b*HH + hd*HS;
    const float* vb = V + b*HH + hd*HS;
    #pragma unroll
    for (int t = 0; t < 2; t++) {
        int f = tid + t*256;
        int row = f >> 4, c4 = (f & 15) << 2;
        float4 q4 = *(const float4*)(qb + row*RS + c4);
        *(float4*)&Qs[row][c4] = q4;
        float4 k4 = *(const float4*)(kb + row*RS + c4);
        KsT[c4+0][row] = k4.x; KsT[c4+1][row] = k4.y;
        KsT[c4+2][row] = k4.z; KsT[c4+3][row] = k4.w;
        float4 v4 = *(const float4*)(vb + row*RS + c4);
        *(float4*)&Vs[row][c4] = v4;
    }
    __syncthreads();
    #pragma unroll
    for (int t = 0; t < 4; t++) {
        int p = tid + t*256;
        int qr = p >> 5, kr = p & 31;
        float sc = 0.f;
        #pragma unroll
        for (int d = 0; d < 64; d++) sc = fmaf(Qs[qr][d], KsT[d][kr], sc);
        P[qr][kr] = sc * 0.125f;
    }
    __syncthreads();
    int w = tid >> 5, lane = tid & 31;
    #pragma unroll
    for (int r = 0; r < 4; r++) {
        int qr = w + r*8;
        bool vq = qr < L, vk = lane < L;
        float v = (vq && vk) ? P[qr][lane] : -1e30f;
        float mx = v;
        #pragma unroll
        for (int off = 16; off > 0; off >>= 1)
            mx = fmaxf(mx, __shfl_xor_sync(0xFFFFFFFFu, mx, off));
        float e = (vq && vk) ? expf(v - mx) : 0.f;
        float sm = e;
        #pragma unroll
        for (int off = 16; off > 0; off >>= 1)
            sm += __shfl_xor_sync(0xFFFFFFFFu, sm, off);
        P[qr][lane] = vq ? (e / sm) : 0.f;
    }
    __syncthreads();
    __nv_bfloat16* ch = ctxh + b*HH + hd*HS;
    __nv_bfloat16* cl = ctxl + b*HH + hd*HS;
    #pragma unroll
    for (int t = 0; t < 8; t++) {
        int e = tid + t*256;
        int qr = e >> 6, d = e & 63;
        float acc = 0.f;
        #pragma unroll
        for (int k = 0; k < 32; k++) acc = fmaf(P[qr][k], Vs[k][d], acc);
        __nv_bfloat16 hi, lo; split2(acc, hi, lo);
        ch[qr*RS + d] = hi;
        cl[qr*RS + d] = lo;
    }
}

// ---------------- LayerNorm(x + y), shuffle reductions, fused split ----------------
__global__ void ln_kernel(const float* __restrict__ X, const float* __restrict__ Y,
                          const float* __restrict__ gam, const float* __restrict__ bet,
                          float* __restrict__ out,
                          __nv_bfloat16* __restrict__ oh, __nv_bfloat16* __restrict__ ol,
                          __nv_bfloat16* __restrict__ ph, __nv_bfloat16* __restrict__ pl)
{
    int row = blockIdx.x;
    int tid = threadIdx.x, wid = tid >> 5, lane = tid & 31;
    const float* x = X + row*HH;
    const float* y = Y + row*HH;
    float v[4];
    float s = 0.f;
    #pragma unroll
    for (int i = 0; i < 4; i++) { v[i] = x[tid + i*256] + y[tid + i*256]; s += v[i]; }
    #pragma unroll
    for (int off = 16; off > 0; off >>= 1) s += __shfl_xor_sync(0xFFFFFFFFu, s, off);
    __shared__ float red[8], red2[8];
    if (lane == 0) red[wid] = s;
    __syncthreads();
    float tot = 0.f;
    #pragma unroll
    for (int wdx = 0; wdx < 8; wdx++) tot += red[wdx];
    float mean = tot * (1.f/1024.f);
    float q = 0.f;
    #pragma unroll
    for (int i = 0; i < 4; i++) { float d = v[i] - mean; q = fmaf(d, d, q); }
    #pragma unroll
    for (int off = 16; off > 0; off >>= 1) q += __shfl_xor_sync(0xFFFFFFFFu, q, off);
    if (lane == 0) red2[wid] = q;
    __syncthreads();
    float tq = 0.f;
    #pragma unroll
    for (int wdx = 0; wdx < 8; wdx++) tq += red2[wdx];
    float inv = rsqrtf(tq * (1.f/1024.f) + 1e-5f);
    #pragma unroll
    for (int i = 0; i < 4; i++) {
        int c = tid + i*256;
        float o = (v[i] - mean) * inv * gam[c] + bet[c];
        out[row*HH + c] = o;
        __nv_bfloat16 hi, lo; split2(o, hi, lo);
        oh[row*HH + c] = hi; ol[row*HH + c] = lo;
        if (ph) { ph[row*HH + c] = hi; pl[row*HH + c] = lo; }
    }
}

// ---------------- r = sigmoid(hf @ Wr), [s][b] layout ----------------
__global__ void r_kernel(const float* __restrict__ h, const float* __restrict__ Wr,
                         float* __restrict__ out_r, int i)
{
    int b = blockIdx.x;
    int tid = threadIdx.x, wid = tid >> 5, lane = tid & 31;
    float acc = 0.f;
    for (int k = tid; k < SQ*HH; k += 256) {
        int s = k >> 10;
        acc = fmaf(h[s*RS + b*HH + (k & 1023)], Wr[k], acc);
    }
    #pragma unroll
    for (int off = 16; off > 0; off >>= 1) acc += __shfl_xor_sync(0xFFFFFFFFu, acc, off);
    __shared__ float red[8];
    if (lane == 0) red[wid] = acc;
    __syncthreads();
    if (tid == 0) {
        float t = 0.f;
        #pragma unroll
        for (int wdx = 0; wdx < 8; wdx++) t += red[wdx];
        out_r[b*TACT + i] = 1.f / (1.f + expf(-t));
    }
}

// ---------------- s_new partials: split-K 32 (one s-position per y-block) ----------------
__global__ void snew_kernel(const float* __restrict__ h, const float* __restrict__ Wso,
                            float* __restrict__ spart)
{
    __shared__ float As[32][36];
    __shared__ float Bs[32][64];
    int tid = threadIdx.x;
    int n0 = blockIdx.x << 6;
    int k0 = blockIdx.y << 10;
    int sblk = blockIdx.y;
    int col = tid & 63;
    int rg  = tid >> 6;
    int ar = tid >> 3, ac4 = (tid & 7) << 2;
    float acc[8] = {};
    for (int kc = 0; kc < 1024; kc += 32) {
        float4 av = *(const float4*)(h + sblk*RS + ar*HH + kc + ac4);
        As[ar][ac4+0] = av.x; As[ar][ac4+1] = av.y;
        As[ar][ac4+2] = av.z; As[ar][ac4+3] = av.w;
        #pragma unroll
        for (int t = 0; t < 2; t++) {
            int f = tid + t*256;
            int kk = f >> 4, c4 = (f & 15) << 2;
            *(float4*)&Bs[kk][c4] = *(const float4*)(Wso + (size_t)(k0 + kc + kk)*HIN + n0 + c4);
        }
        __syncthreads();
        #pragma unroll 8
        for (int kk = 0; kk < 32; kk++) {
            float bv = Bs[kk][col];
            #pragma unroll
            for (int r8 = 0; r8 < 8; r8++)
                acc[r8] = fmaf(As[rg*8 + r8][kk], bv, acc[r8]);
        }
        __syncthreads();
    }
    #pragma unroll
    for (int r8 = 0; r8 < 8; r8++)
        spart[blockIdx.y*(NB*HIN) + (rg*8 + r8)*HIN + n0 + col] = acc[r8];
}

__global__ void fin_kernel(const float* __restrict__ spart, float* __restrict__ srelu,
                           float* __restrict__ out_s, int i)
{
    int idx = blockIdx.x*256 + threadIdx.x;   // 16384
    float v = 0.f;
    #pragma unroll
    for (int p = 0; p < 32; p++) v += spart[p*(NB*HIN) + idx];
    v = fmaxf(v, 0.f);
    srelu[idx] = v;
    int b = idx >> 9, n = idx & 511;
    out_s[(b*TACT + i)*HIN + n] = v;
}

// ---------------- host orchestration ----------------
extern "C" void kernel_launch(void* const* d_in, const int* in_sizes, int n_in,
                              void* d_out, int out_size)
{
    const float* history_s = (const float*)d_in[0];
    const float* history_a = (const float*)d_in[1];
    const float* s_in      = (const float*)d_in[2];
    const float* a_list    = (const float*)d_in[3];
    const float* Ws        = (const float*)d_in[4];
    const float* Wa        = (const float*)d_in[5];
    const float* Wq        = (const float*)d_in[6];
    const float* Wk        = (const float*)d_in[7];
    const float* Wv        = (const float*)d_in[8];
    const float* Wo        = (const float*)d_in[9];
    const float* Wfc       = (const float*)d_in[10];
    const float* ln1_g     = (const float*)d_in[11];
    const float* ln1_b     = (const float*)d_in[12];
    const float* ln2_g     = (const float*)d_in[13];
    const float* ln2_b     = (const float*)d_in[14];
    const float* Wr        = (const float*)d_in[15];
    const float* Wso       = (const float*)d_in[16];

    float* out_r = (float*)d_out;             // [B, TA]
    float* out_s = out_r + NB*TACT;           // [B, TA, HIN]

    void* p;
    cudaGetSymbolAddress(&p, g_pe);     float* pe     = (float*)p;
    cudaGetSymbolAddress(&p, g_tokens); float* tokens = (float*)p;
    cudaGetSymbolAddress(&p, g_h);      float* h      = (float*)p;
    cudaGetSymbolAddress(&p, g_qbuf);   float* qbuf   = (float*)p;
    cudaGetSymbolAddress(&p, g_kbig);   float* kbig   = (float*)p;
    cudaGetSymbolAddress(&p, g_vbuf);   float* vb     = (float*)p;
    cudaGetSymbolAddress(&p, g_tmp);    float* tmp    = (float*)p;
    cudaGetSymbolAddress(&p, g_spart);  float* spart  = (float*)p;
    cudaGetSymbolAddress(&p, g_srelu);  float* srelu  = (float*)p;
    cudaGetSymbolAddress(&p, g_hh);     __nv_bfloat16* hh   = (__nv_bfloat16*)p;
    cudaGetSymbolAddress(&p, g_hl);     __nv_bfloat16* hl   = (__nv_bfloat16*)p;
    cudaGetSymbolAddress(&p, g_ctxh);   __nv_bfloat16* ctxh = (__nv_bfloat16*)p;
    cudaGetSymbolAddress(&p, g_ctxl);   __nv_bfloat16* ctxl = (__nv_bfloat16*)p;
    cudaGetSymbolAddress(&p, g_phh);    __nv_bfloat16* phh  = (__nv_bfloat16*)p;
    cudaGetSymbolAddress(&p, g_phl);    __nv_bfloat16* phl  = (__nv_bfloat16*)p;
    cudaGetSymbolAddress(&p, g_WhT);    __nv_bfloat16* WhT  = (__nv_bfloat16*)p;
    cudaGetSymbolAddress(&p, g_WlT);    __nv_bfloat16* WlT  = (__nv_bfloat16*)p;

    cudaFuncSetAttribute(gemm_tc,   cudaFuncAttributeMaxDynamicSharedMemorySize, GEMM_SMEM);
    cudaFuncSetAttribute(gemm_qkv3, cudaFuncAttributeMaxDynamicSharedMemorySize, GEMM_SMEM);
    cudaFuncSetAttribute(gemm_qk,   cudaFuncAttributeMaxDynamicSharedMemorySize, GEMM_SMEM);

    // side stream + events (fork-join; captured into the graph)
    cudaStream_t s2;
    cudaStreamCreate(&s2);
    cudaEvent_t evLn2[NLAY], evQK[NLAY], evR;
    for (int j = 0; j < NLAY; j++) {
        cudaEventCreateWithFlags(&evLn2[j], cudaEventDisableTiming);
        cudaEventCreateWithFlags(&evQK[j],  cudaEventDisableTiming);
    }
    cudaEventCreateWithFlags(&evR, cudaEventDisableTiming);

    pe_kernel<<<SQ, 256>>>(pe);
    zero4_kernel<<<TOK_ELEMS/1024, 256>>>(tokens);
    wconv_kernel<<<dim3(32, 32, 20), 256>>>(Wq, Wk, Wv, Wo, Wfc, WhT, WlT);

    vecmat_relu<<<dim3(NB*THIST, 4), 256>>>(history_s, HIN, Ws, HIN, 1, 0, tokens);
    vecmat_relu<<<dim3(NB*THIST, 4), 256>>>(history_a, AIN, Wa, AIN, 2, 0, tokens);
    vecmat_relu<<<dim3(NB, 4), 256>>>(s_in, HIN, Ws, HIN, 3, 16, tokens);

    for (int i = 0; i < TACT; i++) {
        int posA = 2*THIST + 1 + 2*i;
        int L = posA + 1;
        int M = NB * L;                 // valid rows (prefix), divisible by 64
        int Mt = M >> 6;                // M-tiles this step
        vecmat_relu<<<dim3(NB, 4), 256>>>(a_list + i*AIN, TACT*AIN, Wa, AIN, 3, posA, tokens);
        if (i > 0) cudaStreamWaitEvent(0, evR, 0);   // r of prev step reads h
        addpe_kernel<<<TOK_ELEMS/256, 256>>>(tokens, pe, h, hh, hl, L);

        for (int j = 0; j < NLAY; j++) {
            float* qbj = qbuf + (size_t)j*TOK_ELEMS;
            float* kbj = kbig + (size_t)j*TOK_ELEMS;
            size_t sq = (size_t)(0*4 + j)*WMAT, sk = (size_t)(1*4 + j)*WMAT;
            size_t sv = (size_t)(2*4 + j)*WMAT, so = (size_t)(3*4 + j)*WMAT;
            size_t sf = (size_t)(4*4 + j)*WMAT;

            if (i == 0) {
                gemm_qkv3<<<dim3(8, Mt, 3), 256, GEMM_SMEM>>>(hh, hl, WhT, WlT,
                                                              sq, sk, sv, qbj, kbj, vb, M);
            } else {
                gemm_tc<<<dim3(8, Mt), 256, GEMM_SMEM>>>(hh, hl, WhT + sv, WlT + sv, vb, M);
                cudaStreamWaitEvent(0, evQK[j], 0);     // Q/K precomputed last step
            }
            attn_kernel<<<NB*NHEAD, 256>>>(L, qbj, kbj, vb, ctxh, ctxl);
            gemm_tc<<<dim3(8, Mt), 256, GEMM_SMEM>>>(ctxh, ctxl, WhT + so, WlT + so, tmp, M);
            ln_kernel<<<M, 256>>>(h, tmp, ln1_g + j*HH, ln1_b + j*HH, h, hh, hl,
                                  (__nv_bfloat16*)0, (__nv_bfloat16*)0);
            gemm_tc<<<dim3(8, Mt), 256, GEMM_SMEM>>>(hh, hl, WhT + sf, WlT + sf, tmp, M);
            ln_kernel<<<M, 256>>>(h, tmp, ln2_g + j*HH, ln2_b + j*HH, h, hh, hl,
                                  phh + (size_t)j*TOK_ELEMS, phl + (size_t)j*TOK_ELEMS);
            cudaEventRecord(evLn2[j], 0);

            if (i + 1 < TACT) {
                // look-ahead Q/K for next step on the side stream (M+64 rows; pad zero-filled)
                cudaStreamWaitEvent(s2, evLn2[j], 0);
                gemm_qk<<<dim3(8, Mt + 1, 2), 256, GEMM_SMEM, s2>>>(
                    phh + (size_t)j*TOK_ELEMS, phl + (size_t)j*TOK_ELEMS,
                    WhT, WlT, sq, sk, qbj, kbj, M);
                cudaEventRecord(evQK[j], s2);
            }
        }
        // r on the side stream (off critical path); snew/fin on main
        if (i + 1 >= TACT) cudaStreamWaitEvent(s2, evLn2[NLAY-1], 0);
        r_kernel<<<NB, 256, 0, s2>>>(h, Wr, out_r, i);
        cudaEventRecord(evR, s2);
        snew_kernel<<<dim3(8, 32), 256>>>(h, Wso, spart);
        fin_kernel<<<64, 256>>>(spart, srelu, out_s, i);
        if (i + 1 < TACT)
            vecmat_relu<<<dim3(NB, 4), 256>>>(srelu, HIN, Ws, HIN, 3, posA + 1, tokens);
    }
    cudaStreamWaitEvent(0, evR, 0);   // join side stream before returning

    for (int j = 0; j < NLAY; j++) {
        cudaEventDestroy(evLn2[j]);
        cudaEventDestroy(evQK[j]);
    }
    cudaEventDestroy(evR);
    cudaStreamDestroy(s2);
}

// round 8
// speedup vs baseline: 3.2354x; 1.1860x over previous
#include <cuda_runtime.h>
#include <cuda_fp16.h>
#include <cstdint>
#include <math.h>

#define NB    32
#define SQ    32
#define HH    1024
#define NHEAD 16
#define HS    64
#define NLAY  4
#define THIST 8
#define TACT  8
#define HIN   512
#define AIN   64
#define RS    (NB*HH)          // 32768: row stride between s-positions

#define TOK_ELEMS (NB*SQ*HH)   // 1048576
#define WMAT      (HH*HH)      // 1048576

// token row layout: row = s*NB + b  (valid rows are prefix [0, 32*L))

// ---------------- scratch (device globals; no allocation) ----------------
__device__ float g_pe[SQ*HH];
__device__ float g_tokens[TOK_ELEMS];
__device__ float g_h[TOK_ELEMS];
__device__ float g_qbuf[NLAY*TOK_ELEMS];   // per-layer Q
__device__ float g_kbig[NLAY*TOK_ELEMS];   // per-layer K
__device__ float g_vbuf[TOK_ELEMS];
__device__ float g_tmp[TOK_ELEMS];
__device__ float g_spart[32*NB*HIN];
__device__ float g_srelu[NB*HIN];
__device__ __half g_hh[TOK_ELEMS];                 // fp16 activations
__device__ __half g_ctxh[TOK_ELEMS];
__device__ __half g_phh[NLAY*TOK_ELEMS];
__device__ __half g_WhT[20*WMAT];                  // fp16 weight hi [N,K]
__device__ __half g_WlT[20*WMAT];                  // fp16 weight lo [N,K]

// ---------------- helpers ----------------
__device__ __forceinline__ uint32_t s2u(const void* p) {
    uint32_t a;
    asm("{ .reg .u64 t; cvta.to.shared.u64 t, %1; cvt.u32.u64 %0, t; }" : "=r"(a) : "l"(p));
    return a;
}

#define LDM4(r, addr) \
    asm volatile("ldmatrix.sync.aligned.m8n8.x4.shared.b16 {%0,%1,%2,%3}, [%4];" \
        : "=r"((r)[0]), "=r"((r)[1]), "=r"((r)[2]), "=r"((r)[3]) : "r"(addr))

#define MMA_F16(d, a, b0v, b1v) \
    asm volatile("mma.sync.aligned.m16n8k16.row.col.f32.f16.f16.f32 " \
        "{%0,%1,%2,%3}, {%4,%5,%6,%7}, {%8,%9}, {%0,%1,%2,%3};" \
        : "+f"((d)[0]), "+f"((d)[1]), "+f"((d)[2]), "+f"((d)[3]) \
        : "r"((a)[0]), "r"((a)[1]), "r"((a)[2]), "r"((a)[3]), "r"(b0v), "r"(b1v))

#define CP_ASYNC16(sa, gp) \
    asm volatile("cp.async.cg.shared.global [%0], [%1], 16;" :: "r"(sa), "l"(gp))
#define CP_ASYNC16Z(sa, gp, sz) \
    asm volatile("cp.async.cg.shared.global [%0], [%1], 16, %2;" :: "r"(sa), "l"(gp), "r"(sz))
#define CP_COMMIT()  asm volatile("cp.async.commit_group;" ::: "memory")
#define CP_WAIT0()   asm volatile("cp.async.wait_group 0;" ::: "memory")
#define CP_WAIT1()   asm volatile("cp.async.wait_group 1;" ::: "memory")
#define CP_WAIT2()   asm volatile("cp.async.wait_group 2;" ::: "memory")

// ---------------- weight transpose + fp16 split: W[K,N] -> WT[N,K] hi/lo ----------------
__global__ void wconv_kernel(const float* __restrict__ Wq, const float* __restrict__ Wk,
                             const float* __restrict__ Wv, const float* __restrict__ Wo,
                             const float* __restrict__ Wfc,
                             __half* __restrict__ WhT, __half* __restrict__ WlT)
{
    int z = blockIdx.z;                 // 0..19 = type*4 + layer
    int type = z >> 2, layer = z & 3;
    const float* bases[5] = {Wq, Wk, Wv, Wo, Wfc};
    const float* W = bases[type] + (size_t)layer * WMAT;
    __shared__ float t[32][33];
    int x0 = blockIdx.x * 32;  // K
    int y0 = blockIdx.y * 32;  // N
    int tr = threadIdx.x >> 5, tc = threadIdx.x & 31;
    #pragma unroll
    for (int u = 0; u < 4; u++) {
        int r = tr + u * 8;
        t[r][tc] = W[(size_t)(x0 + r) * HH + y0 + tc];
    }
    __syncthreads();
    size_t ob = (size_t)z * WMAT;
    #pragma unroll
    for (int u = 0; u < 4; u++) {
        int r = tr + u * 8;
        float v = t[tc][r];
        __half hi = __float2half(v);
        __half lo = __float2half(v - __half2float(hi));
        size_t off = ob + (size_t)(y0 + r) * HH + x0 + tc;
        WhT[off] = hi;
        WlT[off] = lo;
    }
}

// ---------------- fp16 2-term tensor-core GEMM (mma.sync) ----------------
// C[M,1024] = A x (Wh + Wl)^T.  A fp16 [M,K]; W stored [N,K] hi/lo.
// CTA tile 64(M) x 128(N), K-chunk 64, 4-buffer/3-outstanding cp.async pipeline.
// Stage (40960 B): A[0,8K) Bh[8K,24K) Bl[24K,40K)
#define STAGE 40960
#define NBUF  4
#define GEMM_SMEM (NBUF*STAGE)    // 163840

__device__ __forceinline__ void issue_stage(uint32_t sbase, int buf,
    const __half* __restrict__ A,
    const __half* __restrict__ Bh, const __half* __restrict__ Bl,
    int bm, int bn, int k0, int tid, int mvalid)
{
    uint32_t st = sbase + buf * STAGE;
    #pragma unroll
    for (int u = 0; u < 10; u++) {
        int id = tid + u * 256;
        if (id < 512) {
            int r = id >> 3, c = id & 7;
            const __half* gp = A + (size_t)(bm + r) * HH + k0 + c * 8;
            uint32_t sa = st + r * 128 + ((c ^ (r & 7)) << 4);
            uint32_t sz = ((bm + r) < mvalid) ? 16u : 0u;
            CP_ASYNC16Z(sa, gp, sz);
        } else {
            int sec = (id - 512) >> 10;      // 0=Bh 1=Bl
            int t = (id - 512) & 1023;
            int r = t >> 3, c = t & 7;
            const __half* gp = (sec ? Bl : Bh) + (size_t)(bn + r) * HH + k0 + c * 8;
            uint32_t sa = st + 8192 + sec * 16384 + r * 128 + ((c ^ (r & 7)) << 4);
            CP_ASYNC16(sa, gp);
        }
    }
    CP_COMMIT();
}

__device__ __forceinline__ void gemm_body(
    const __half* __restrict__ A,
    const __half* __restrict__ Bh, const __half* __restrict__ Bl,
    float* __restrict__ C, int mvalid)
{
    extern __shared__ char smem[];
    uint32_t sbase = s2u(smem);
    int tid = threadIdx.x, wid = tid >> 5, lane = tid & 31;
    int bm = blockIdx.y << 6, bn = blockIdx.x << 7;
    int warpM = (wid >> 2) << 5;
    int warpN = (wid & 3) << 5;

    issue_stage(sbase, 0, A, Bh, Bl, bm, bn, 0,   tid, mvalid);
    issue_stage(sbase, 1, A, Bh, Bl, bm, bn, 64,  tid, mvalid);
    issue_stage(sbase, 2, A, Bh, Bl, bm, bn, 128, tid, mvalid);

    float acc[2][4][4] = {};

    for (int s = 0; s < 16; s++) {
        if (s < 14)       { CP_WAIT2(); }
        else if (s == 14) { CP_WAIT1(); }
        else              { CP_WAIT0(); }
        __syncthreads();
        if (s + 3 < 16)
            issue_stage(sbase, (s + 3) & 3, A, Bh, Bl, bm, bn, (s + 3) << 6, tid, mvalid);
        uint32_t st = sbase + (s & 3) * STAGE;
        #pragma unroll
        for (int kk = 0; kk < 4; kk++) {
            uint32_t ah[2][4];
            #pragma unroll
            for (int mt = 0; mt < 2; mt++) {
                int r = warpM + mt * 16 + (lane & 15);
                int ch = kk * 2 + (lane >> 4);
                uint32_t ad = st + r * 128 + ((ch ^ (r & 7)) << 4);
                LDM4(ah[mt], ad);
            }
            uint32_t bh[2][4], bl[2][4];
            #pragma unroll
            for (int nt = 0; nt < 2; nt++) {
                int r = warpN + nt * 16 + (lane & 7) + ((lane >> 4) << 3);
                int ch = kk * 2 + ((lane >> 3) & 1);
                uint32_t bd = st + 8192 + r * 128 + ((ch ^ (r & 7)) << 4);
                LDM4(bh[nt], bd);
                LDM4(bl[nt], bd + 16384);
            }
            #pragma unroll
            for (int mt = 0; mt < 2; mt++) {
                #pragma unroll
                for (int j = 0; j < 4; j++) {
                    uint32_t b0 = bh[j >> 1][(j & 1) * 2], b1 = bh[j >> 1][(j & 1) * 2 + 1];
                    uint32_t c0 = bl[j >> 1][(j & 1) * 2], c1 = bl[j >> 1][(j & 1) * 2 + 1];
                    MMA_F16(acc[mt][j], ah[mt], b0, b1);
                    MMA_F16(acc[mt][j], ah[mt], c0, c1);
                }
            }
        }
    }

    #pragma unroll
    for (int mt = 0; mt < 2; mt++) {
        int row = bm + warpM + mt * 16 + (lane >> 2);
        #pragma unroll
        for (int j = 0; j < 4; j++) {
            int col = bn + warpN + j * 8 + ((lane & 3) << 1);
            *(float2*)&C[(size_t)row * HH + col] =
                make_float2(acc[mt][j][0], acc[mt][j][1]);
            *(float2*)&C[(size_t)(row + 8) * HH + col] =
                make_float2(acc[mt][j][2], acc[mt][j][3]);
        }
    }
}

__global__ void __launch_bounds__(256, 1) gemm_tc(
    const __half* __restrict__ A,
    const __half* __restrict__ Bh, const __half* __restrict__ Bl,
    float* __restrict__ C, int mvalid)
{
    gemm_body(A, Bh, Bl, C, mvalid);
}

// step-0 QKV: all operands from current hh
__global__ void __launch_bounds__(256, 1) gemm_qkv3(
    const __half* __restrict__ hh,
    const __half* __restrict__ WhT, const __half* __restrict__ WlT,
    size_t sq, size_t sk, size_t sv,
    float* __restrict__ Q, float* __restrict__ K, float* __restrict__ V, int mvalid)
{
    int z = blockIdx.z;
    size_t off = (z == 0) ? sq : (z == 1) ? sk : sv;
    float* C = (z == 0) ? Q : (z == 1) ? K : V;
    gemm_body(hh, WhT + off, WlT + off, C, mvalid);
}

// look-ahead Q,K for next step from prev_h[j]
__global__ void __launch_bounds__(256, 1) gemm_qk(
    const __half* __restrict__ ph,
    const __half* __restrict__ WhT, const __half* __restrict__ WlT,
    size_t sq, size_t sk,
    float* __restrict__ Q, float* __restrict__ K, int mvalid)
{
    int z = blockIdx.z;
    size_t off = (z == 0) ? sq : sk;
    float* C = (z == 0) ? Q : K;
    gemm_body(ph, WhT + off, WlT + off, C, mvalid);
}

// ---------------- positional encoding ----------------
__global__ void pe_kernel(float* __restrict__ pe)
{
    int s = blockIdx.x;
    for (int h = threadIdx.x; h < HH; h += 256) {
        float e = (float)(2 * (h / 2)) * (1.0f / HH);
        float freq = exp2f(-e * 13.287712379549449f);   // log2(10000)
        float angle = (float)s * freq;
        pe[s*HH + h] = (h & 1) ? cosf(angle) : sinf(angle);
    }
}

__global__ void zero4_kernel(float* __restrict__ p)
{
    int idx = blockIdx.x*256 + threadIdx.x;
    ((float4*)p)[idx] = make_float4(0.f,0.f,0.f,0.f);
}

// ---------------- small row GEMM + relu into tokens ([s][b] layout) ----------------
__global__ void vecmat_relu(const float* __restrict__ X, int xstride,
                            const float* __restrict__ W, int K,
                            int mode, int off, float* __restrict__ tokens)
{
    int r = blockIdx.x;
    __shared__ float xs[512];
    for (int k = threadIdx.x; k < K; k += 256) xs[k] = X[r*xstride + k];
    __syncthreads();
    int drow;
    if      (mode == 1) drow = (2*(r&7))*NB + (r>>3);
    else if (mode == 2) drow = (2*(r&7)+1)*NB + (r>>3);
    else                drow = off*NB + r;
    int c = blockIdx.y*256 + threadIdx.x;
    float acc = 0.f;
    for (int k = 0; k < K; k++) acc = fmaf(xs[k], W[k*HH + c], acc);
    tokens[drow*HH + c] = fmaxf(acc, 0.f);
}

// ---------------- h = tokens + pe (valid rows), fused fp16 convert ----------------
__global__ void addpe_kernel(const float* __restrict__ tokens,
                             const float* __restrict__ pe,
                             float* __restrict__ h,
                             __half* __restrict__ hh, int L)
{
    int i = blockIdx.x*256 + threadIdx.x;
    float v = tokens[i];
    int srow = i >> 15;                       // s index ([s][b] layout)
    if (srow < L) v += pe[srow*HH + (i & 1023)];
    h[i] = v;
    hh[i] = __float2half(v);
}

// ---------------- attention (one block per (b, head)), [s][b] layout ----------------
__global__ void attn_kernel(int L, const float* __restrict__ Q,
                            const float* __restrict__ K,
                            const float* __restrict__ V,
                            __half* __restrict__ ctxh)
{
    __shared__ float Qs[32][64];
    __shared__ float KsT[64][33];
    __shared__ float Vs[32][64];
    __shared__ float P[32][33];
    int tid = threadIdx.x;
    int b = blockIdx.x >> 4, hd = blockIdx.x & 15;
    const float* qb = Q + b*HH + hd*HS;
    const float* kb = K + b*HH + hd*HS;
    const float* vb = V + b*HH + hd*HS;
    #pragma unroll
    for (int t = 0; t < 2; t++) {
        int f = tid + t*256;
        int row = f >> 4, c4 = (f & 15) << 2;
        float4 q4 = *(const float4*)(qb + row*RS + c4);
        *(float4*)&Qs[row][c4] = q4;
        float4 k4 = *(const float4*)(kb + row*RS + c4);
        KsT[c4+0][row] = k4.x; KsT[c4+1][row] = k4.y;
        KsT[c4+2][row] = k4.z; KsT[c4+3][row] = k4.w;
        float4 v4 = *(const float4*)(vb + row*RS + c4);
        *(float4*)&Vs[row][c4] = v4;
    }
    __syncthreads();
    #pragma unroll
    for (int t = 0; t < 4; t++) {
        int p = tid + t*256;
        int qr = p >> 5, kr = p & 31;
        float sc = 0.f;
        #pragma unroll
        for (int d = 0; d < 64; d++) sc = fmaf(Qs[qr][d], KsT[d][kr], sc);
        P[qr][kr] = sc * 0.125f;
    }
    __syncthreads();
    int w = tid >> 5, lane = tid & 31;
    #pragma unroll
    for (int r = 0; r < 4; r++) {
        int qr = w + r*8;
        bool vq = qr < L, vk = lane < L;
        float v = (vq && vk) ? P[qr][lane] : -1e30f;
        float mx = v;
        #pragma unroll
        for (int off = 16; off > 0; off >>= 1)
            mx = fmaxf(mx, __shfl_xor_sync(0xFFFFFFFFu, mx, off));
        float e = (vq && vk) ? expf(v - mx) : 0.f;
        float sm = e;
        #pragma unroll
        for (int off = 16; off > 0; off >>= 1)
            sm += __shfl_xor_sync(0xFFFFFFFFu, sm, off);
        P[qr][lane] = vq ? (e / sm) : 0.f;
    }
    __syncthreads();
    __half* ch = ctxh + b*HH + hd*HS;
    #pragma unroll
    for (int t = 0; t < 8; t++) {
        int e = tid + t*256;
        int qr = e >> 6, d = e & 63;
        float acc = 0.f;
        #pragma unroll
        for (int k = 0; k < 32; k++) acc = fmaf(P[qr][k], Vs[k][d], acc);
        ch[qr*RS + d] = __float2half(acc);
    }
}

// ---------------- LayerNorm(x + y), shuffle reductions, fused fp16 convert ----------------
__global__ void ln_kernel(const float* __restrict__ X, const float* __restrict__ Y,
                          const float* __restrict__ gam, const float* __restrict__ bet,
                          float* __restrict__ out,
                          __half* __restrict__ oh, __half* __restrict__ ph)
{
    int row = blockIdx.x;
    int tid = threadIdx.x, wid = tid >> 5, lane = tid & 31;
    const float* x = X + row*HH;
    const float* y = Y + row*HH;
    float v[4];
    float s = 0.f;
    #pragma unroll
    for (int i = 0; i < 4; i++) { v[i] = x[tid + i*256] + y[tid + i*256]; s += v[i]; }
    #pragma unroll
    for (int off = 16; off > 0; off >>= 1) s += __shfl_xor_sync(0xFFFFFFFFu, s, off);
    __shared__ float red[8], red2[8];
    if (lane == 0) red[wid] = s;
    __syncthreads();
    float tot = 0.f;
    #pragma unroll
    for (int wdx = 0; wdx < 8; wdx++) tot += red[wdx];
    float mean = tot * (1.f/1024.f);
    float q = 0.f;
    #pragma unroll
    for (int i = 0; i < 4; i++) { float d = v[i] - mean; q = fmaf(d, d, q); }
    #pragma unroll
    for (int off = 16; off > 0; off >>= 1) q += __shfl_xor_sync(0xFFFFFFFFu, q, off);
    if (lane == 0) red2[wid] = q;
    __syncthreads();
    float tq = 0.f;
    #pragma unroll
    for (int wdx = 0; wdx < 8; wdx++) tq += red2[wdx];
    float inv = rsqrtf(tq * (1.f/1024.f) + 1e-5f);
    #pragma unroll
    for (int i = 0; i < 4; i++) {
        int c = tid + i*256;
        float o = (v[i] - mean) * inv * gam[c] + bet[c];
        out[row*HH + c] = o;
        __half hv = __float2half(o);
        oh[row*HH + c] = hv;
        if (ph) ph[row*HH + c] = hv;
    }
}

// ---------------- r = sigmoid(hf @ Wr), [s][b] layout ----------------
__global__ void r_kernel(const float* __restrict__ h, const float* __restrict__ Wr,
                         float* __restrict__ out_r, int i)
{
    int b = blockIdx.x;
    int tid = threadIdx.x, wid = tid >> 5, lane = tid & 31;
    float acc = 0.f;
    for (int k = tid; k < SQ*HH; k += 256) {
        int s = k >> 10;
        acc = fmaf(h[s*RS + b*HH + (k & 1023)], Wr[k], acc);
    }
    #pragma unroll
    for (int off = 16; off > 0; off >>= 1) acc += __shfl_xor_sync(0xFFFFFFFFu, acc, off);
    __shared__ float red[8];
    if (lane == 0) red[wid] = acc;
    __syncthreads();
    if (tid == 0) {
        float t = 0.f;
        #pragma unroll
        for (int wdx = 0; wdx < 8; wdx++) t += red[wdx];
        out_r[b*TACT + i] = 1.f / (1.f + expf(-t));
    }
}

// ---------------- s_new partials: split-K 32 (one s-position per y-block) ----------------
__global__ void snew_kernel(const float* __restrict__ h, const float* __restrict__ Wso,
                            float* __restrict__ spart)
{
    __shared__ float As[32][36];
    __shared__ float Bs[32][64];
    int tid = threadIdx.x;
    int n0 = blockIdx.x << 6;
    int k0 = blockIdx.y << 10;
    int sblk = blockIdx.y;
    int col = tid & 63;
    int rg  = tid >> 6;
    int ar = tid >> 3, ac4 = (tid & 7) << 2;
    float acc[8] = {};
    for (int kc = 0; kc < 1024; kc += 32) {
        float4 av = *(const float4*)(h + sblk*RS + ar*HH + kc + ac4);
        As[ar][ac4+0] = av.x; As[ar][ac4+1] = av.y;
        As[ar][ac4+2] = av.z; As[ar][ac4+3] = av.w;
        #pragma unroll
        for (int t = 0; t < 2; t++) {
            int f = tid + t*256;
            int kk = f >> 4, c4 = (f & 15) << 2;
            *(float4*)&Bs[kk][c4] = *(const float4*)(Wso + (size_t)(k0 + kc + kk)*HIN + n0 + c4);
        }
        __syncthreads();
        #pragma unroll 8
        for (int kk = 0; kk < 32; kk++) {
            float bv = Bs[kk][col];
            #pragma unroll
            for (int r8 = 0; r8 < 8; r8++)
                acc[r8] = fmaf(As[rg*8 + r8][kk], bv, acc[r8]);
        }
        __syncthreads();
    }
    #pragma unroll
    for (int r8 = 0; r8 < 8; r8++)
        spart[blockIdx.y*(NB*HIN) + (rg*8 + r8)*HIN + n0 + col] = acc[r8];
}

__global__ void fin_kernel(const float* __restrict__ spart, float* __restrict__ srelu,
                           float* __restrict__ out_s, int i)
{
    int idx = blockIdx.x*256 + threadIdx.x;   // 16384
    float v = 0.f;
    #pragma unroll
    for (int p = 0; p < 32; p++) v += spart[p*(NB*HIN) + idx];
    v = fmaxf(v, 0.f);
    srelu[idx] = v;
    int b = idx >> 9, n = idx & 511;
    out_s[(b*TACT + i)*HIN + n] = v;
}

// ---------------- host orchestration ----------------
extern "C" void kernel_launch(void* const* d_in, const int* in_sizes, int n_in,
                              void* d_out, int out_size)
{
    const float* history_s = (const float*)d_in[0];
    const float* history_a = (const float*)d_in[1];
    const float* s_in      = (const float*)d_in[2];
    const float* a_list    = (const float*)d_in[3];
    const float* Ws        = (const float*)d_in[4];
    const float* Wa        = (const float*)d_in[5];
    const float* Wq        = (const float*)d_in[6];
    const float* Wk        = (const float*)d_in[7];
    const float* Wv        = (const float*)d_in[8];
    const float* Wo        = (const float*)d_in[9];
    const float* Wfc       = (const float*)d_in[10];
    const float* ln1_g     = (const float*)d_in[11];
    const float* ln1_b     = (const float*)d_in[12];
    const float* ln2_g     = (const float*)d_in[13];
    const float* ln2_b     = (const float*)d_in[14];
    const float* Wr        = (const float*)d_in[15];
    const float* Wso       = (const float*)d_in[16];

    float* out_r = (float*)d_out;             // [B, TA]
    float* out_s = out_r + NB*TACT;           // [B, TA, HIN]

    void* p;
    cudaGetSymbolAddress(&p, g_pe);     float* pe     = (float*)p;
    cudaGetSymbolAddress(&p, g_tokens); float* tokens = (float*)p;
    cudaGetSymbolAddress(&p, g_h);      float* h      = (float*)p;
    cudaGetSymbolAddress(&p, g_qbuf);   float* qbuf   = (float*)p;
    cudaGetSymbolAddress(&p, g_kbig);   float* kbig   = (float*)p;
    cudaGetSymbolAddress(&p, g_vbuf);   float* vb     = (float*)p;
    cudaGetSymbolAddress(&p, g_tmp);    float* tmp    = (float*)p;
    cudaGetSymbolAddress(&p, g_spart);  float* spart  = (float*)p;
    cudaGetSymbolAddress(&p, g_srelu);  float* srelu  = (float*)p;
    cudaGetSymbolAddress(&p, g_hh);     __half* hh   = (__half*)p;
    cudaGetSymbolAddress(&p, g_ctxh);   __half* ctxh = (__half*)p;
    cudaGetSymbolAddress(&p, g_phh);    __half* phh  = (__half*)p;
    cudaGetSymbolAddress(&p, g_WhT);    __half* WhT  = (__half*)p;
    cudaGetSymbolAddress(&p, g_WlT);    __half* WlT  = (__half*)p;

    cudaFuncSetAttribute(gemm_tc,   cudaFuncAttributeMaxDynamicSharedMemorySize, GEMM_SMEM);
    cudaFuncSetAttribute(gemm_qkv3, cudaFuncAttributeMaxDynamicSharedMemorySize, GEMM_SMEM);
    cudaFuncSetAttribute(gemm_qk,   cudaFuncAttributeMaxDynamicSharedMemorySize, GEMM_SMEM);

    // side stream + events (fork-join; captured into the graph)
    cudaStream_t s2;
    cudaStreamCreate(&s2);
    cudaEvent_t evLn2[NLAY], evQK[NLAY], evR;
    for (int j = 0; j < NLAY; j++) {
        cudaEventCreateWithFlags(&evLn2[j], cudaEventDisableTiming);
        cudaEventCreateWithFlags(&evQK[j],  cudaEventDisableTiming);
    }
    cudaEventCreateWithFlags(&evR, cudaEventDisableTiming);

    pe_kernel<<<SQ, 256>>>(pe);
    zero4_kernel<<<TOK_ELEMS/1024, 256>>>(tokens);
    wconv_kernel<<<dim3(32, 32, 20), 256>>>(Wq, Wk, Wv, Wo, Wfc, WhT, WlT);

    vecmat_relu<<<dim3(NB*THIST, 4), 256>>>(history_s, HIN, Ws, HIN, 1, 0, tokens);
    vecmat_relu<<<dim3(NB*THIST, 4), 256>>>(history_a, AIN, Wa, AIN, 2, 0, tokens);
    vecmat_relu<<<dim3(NB, 4), 256>>>(s_in, HIN, Ws, HIN, 3, 16, tokens);

    for (int i = 0; i < TACT; i++) {
        int posA = 2*THIST + 1 + 2*i;
        int L = posA + 1;
        int M = NB * L;                 // valid rows (prefix), divisible by 64
        int Mt = M >> 6;                // M-tiles this step
        vecmat_relu<<<dim3(NB, 4), 256>>>(a_list + i*AIN, TACT*AIN, Wa, AIN, 3, posA, tokens);
        if (i > 0) cudaStreamWaitEvent(0, evR, 0);   // r of prev step reads h
        addpe_kernel<<<TOK_ELEMS/256, 256>>>(tokens, pe, h, hh, L);

        for (int j = 0; j < NLAY; j++) {
            float* qbj = qbuf + (size_t)j*TOK_ELEMS;
            float* kbj = kbig + (size_t)j*TOK_ELEMS;
            size_t sq = (size_t)(0*4 + j)*WMAT, sk = (size_t)(1*4 + j)*WMAT;
            size_t sv = (size_t)(2*4 + j)*WMAT, so = (size_t)(3*4 + j)*WMAT;
            size_t sf = (size_t)(4*4 + j)*WMAT;

            if (i == 0) {
                gemm_qkv3<<<dim3(8, Mt, 3), 256, GEMM_SMEM>>>(hh, WhT, WlT,
                                                              sq, sk, sv, qbj, kbj, vb, M);
            } else {
                gemm_tc<<<dim3(8, Mt), 256, GEMM_SMEM>>>(hh, WhT + sv, WlT + sv, vb, M);
                cudaStreamWaitEvent(0, evQK[j], 0);     // Q/K precomputed last step
            }
            attn_kernel<<<NB*NHEAD, 256>>>(L, qbj, kbj, vb, ctxh);
            gemm_tc<<<dim3(8, Mt), 256, GEMM_SMEM>>>(ctxh, WhT + so, WlT + so, tmp, M);
            ln_kernel<<<M, 256>>>(h, tmp, ln1_g + j*HH, ln1_b + j*HH, h, hh, (__half*)0);
            gemm_tc<<<dim3(8, Mt), 256, GEMM_SMEM>>>(hh, WhT + sf, WlT + sf, tmp, M);
            ln_kernel<<<M, 256>>>(h, tmp, ln2_g + j*HH, ln2_b + j*HH, h, hh,
                                  phh + (size_t)j*TOK_ELEMS);
            cudaEventRecord(evLn2[j], 0);

            if (i + 1 < TACT) {
                // look-ahead Q/K for next step on the side stream (M+64 rows; pad zero-filled)
                cudaStreamWaitEvent(s2, evLn2[j], 0);
                gemm_qk<<<dim3(8, Mt + 1, 2), 256, GEMM_SMEM, s2>>>(
                    phh + (size_t)j*TOK_ELEMS, WhT, WlT, sq, sk, qbj, kbj, M);
                cudaEventRecord(evQK[j], s2);
            }
        }
        // r on the side stream (off critical path); snew/fin on main
        if (i + 1 >= TACT) cudaStreamWaitEvent(s2, evLn2[NLAY-1], 0);
        r_kernel<<<NB, 256, 0, s2>>>(h, Wr, out_r, i);
        cudaEventRecord(evR, s2);
        snew_kernel<<<dim3(8, 32), 256>>>(h, Wso, spart);
        fin_kernel<<<64, 256>>>(spart, srelu, out_s, i);
        if (i + 1 < TACT)
            vecmat_relu<<<dim3(NB, 4), 256>>>(srelu, HIN, Ws, HIN, 3, posA + 1, tokens);
    }
    cudaStreamWaitEvent(0, evR, 0);   // join side stream before returning

    for (int j = 0; j < NLAY; j++) {
        cudaEventDestroy(evLn2[j]);
        cudaEventDestroy(evQK[j]);
    }
    cudaEventDestroy(evR);
    cudaStreamDestroy(s2);
}